// round 8
// baseline (speedup 1.0000x reference)
#include <cuda_runtime.h>

#define NN 50000
#define EE 800000
#define TEg (EE + NN)          // edges + self loops
#define NEG_SLOPE 0.2f

// -------- static device scratch (no allocations allowed) --------
__device__ __align__(16) float g_h[NN * 64];     // GEMM output (h of current layer)
__device__ __align__(16) float g_act[NN * 64];   // layer-1 activated output
__device__ float g_as[NN];
__device__ float g_ad[NN];
__device__ int   g_cnt[NN];
__device__ int   g_rowptr[NN + 1];
__device__ int   g_cursor[NN];
__device__ int   g_srcidx[TEg];
__device__ int   g_bsums[128];
__device__ int   g_is64;           // 1 if edge_index buffer is int64, 0 if int32

// ---------------- init + dtype detection (fused) ----------------
// Blocks [0, NB-2] zero g_cnt; the last block detects the edge-index dtype:
// if int64, odd 32-bit words (high halves) are all 0 (indices < 50000).
__global__ void k_init(const int* __restrict__ ei32) {
    if ((int)blockIdx.x == (int)gridDim.x - 1) {
        __shared__ int sm[256];
        int t = threadIdx.x;
        int acc = 0;
        for (int i = t; i < 32768; i += 256)
            acc |= ei32[2 * i + 1];
        sm[t] = acc;
        __syncthreads();
        for (int off = 128; off; off >>= 1) {
            if (t < off) sm[t] |= sm[t + off];
            __syncthreads();
        }
        if (t == 0) g_is64 = (sm[0] == 0) ? 1 : 0;
        return;
    }
    int i = blockIdx.x * 256 + threadIdx.x;
    for (; i < NN; i += (gridDim.x - 1) * 256) g_cnt[i] = 0;
}

__device__ __forceinline__ int load_idx(const void* ei, long long pos) {
    if (g_is64) return (int)((const long long*)ei)[pos];
    return ((const int*)ei)[pos];
}

// ---------------- CSR build ----------------
__global__ void k_hist(const void* __restrict__ ei) {
    int i = blockIdx.x * blockDim.x + threadIdx.x;
    if (i >= TEg) return;
    int d = (i < EE) ? load_idx(ei, (long long)EE + i) : (i - EE);
    if (d >= 0 && d < NN) atomicAdd(&g_cnt[d], 1);
}

// block-level inclusive scan (shfl-based), 512 threads per block
__global__ void k_scan1() {
    __shared__ int wsum[16];
    int t = threadIdx.x;
    int lane = t & 31, wid = t >> 5;
    int i = blockIdx.x * 512 + t;
    int v = (i < NN) ? g_cnt[i] : 0;

    int s = v;
    #pragma unroll
    for (int off = 1; off < 32; off <<= 1) {
        int n = __shfl_up_sync(0xffffffffu, s, off);
        if (lane >= off) s += n;
    }
    if (lane == 31) wsum[wid] = s;
    __syncthreads();
    if (wid == 0) {
        int ws = (lane < 16) ? wsum[lane] : 0;
        #pragma unroll
        for (int off = 1; off < 16; off <<= 1) {
            int n = __shfl_up_sync(0xffffffffu, ws, off);
            if (lane >= off) ws += n;
        }
        if (lane < 16) wsum[lane] = ws;
    }
    __syncthreads();
    int base = (wid > 0) ? wsum[wid - 1] : 0;
    s += base;
    if (i < NN) g_rowptr[i + 1] = s;
    if (t == 511) g_bsums[blockIdx.x] = s;
}

// add block offsets; every block redundantly scans the 98 block sums (cheap)
__global__ void k_scan3(int nblocks) {
    __shared__ int boff[128];
    int t = threadIdx.x;            // 256 threads
    if (t < 128) {
        int lane = t & 31, wid = t >> 5;
        int v = (t < nblocks) ? g_bsums[t] : 0;
        int s = v;
        #pragma unroll
        for (int off = 1; off < 32; off <<= 1) {
            int n = __shfl_up_sync(0xffffffffu, s, off);
            if (lane >= off) s += n;
        }
        boff[t] = s;                // partial per-warp inclusive
        // combine 4 warps serially via shared (tiny)
    }
    __syncthreads();
    if (t == 0) {
        int add = 0;
        for (int w = 0; w < 4; ++w) {
            int last = boff[w * 32 + 31];
            if (w > 0)
                for (int j = 0; j < 32; ++j) boff[w * 32 + j] += add;
            add += (w > 0) ? last : boff[31] - 0;
            if (w == 0) add = boff[31];
        }
    }
    __syncthreads();
    int i = blockIdx.x * 256 + t;
    if (i == 0) { g_rowptr[0] = 0; g_cursor[0] = 0; }
    if (i < NN) {
        int blk = i >> 9;
        int off = (blk > 0) ? boff[blk - 1] : 0;
        int v = g_rowptr[i + 1] + off;
        g_rowptr[i + 1] = v;
        if (i + 1 < NN) g_cursor[i + 1] = v;
    }
}

__global__ void k_scatter(const void* __restrict__ ei) {
    int i = blockIdx.x * blockDim.x + threadIdx.x;
    if (i >= TEg) return;
    int s, d;
    if (i < EE) {
        s = load_idx(ei, i);
        d = load_idx(ei, (long long)EE + i);
    } else {
        s = i - EE; d = s;
    }
    if (d < 0 || d >= NN || s < 0 || s >= NN) return;
    int pos = atomicAdd(&g_cursor[d], 1);
    if (pos >= 0 && pos < TEg) g_srcidx[pos] = s;
}

// ---------------- fused GEMM + attention projections ----------------
// H[N,64] = X[N,FIN] @ W[FIN,64];  g_as[n] = H[n]·a_src;  g_ad[n] = H[n]·a_dst
template <int FIN, bool USE_ACT>
__global__ __launch_bounds__(256)
void k_gemm(const float* __restrict__ Xext, const float* __restrict__ W,
            const float* __restrict__ a_src, const float* __restrict__ a_dst) {
    __shared__ float Xs[64][36];
    __shared__ float Ws[32][68];

    const float* X = USE_ACT ? (const float*)g_act : Xext;

    int tid = threadIdx.x;
    int tx = tid & 15, ty = tid >> 4;
    int row0 = blockIdx.x * 64;

    float acc[4][4] = {};

    for (int k0 = 0; k0 < FIN; k0 += 32) {
        #pragma unroll
        for (int l = 0; l < 2; ++l) {
            int idx = l * 256 + tid;
            int r = idx >> 3, kk4 = idx & 7;
            int row = row0 + r;
            float4 v = make_float4(0.f, 0.f, 0.f, 0.f);
            if (row < NN) v = *(const float4*)(X + (size_t)row * FIN + k0 + kk4 * 4);
            *(float4*)(&Xs[r][kk4 * 4]) = v;
        }
        #pragma unroll
        for (int l = 0; l < 2; ++l) {
            int idx = l * 256 + tid;
            int k = idx >> 4, c4 = idx & 15;
            float4 v = *(const float4*)(W + (size_t)(k0 + k) * 64 + c4 * 4);
            *(float4*)(&Ws[k][c4 * 4]) = v;
        }
        __syncthreads();

        #pragma unroll
        for (int kk = 0; kk < 32; ++kk) {
            float4 wv = *(const float4*)(&Ws[kk][tx * 4]);
            float xv[4];
            #pragma unroll
            for (int r = 0; r < 4; ++r) xv[r] = Xs[ty * 4 + r][kk];
            #pragma unroll
            for (int r = 0; r < 4; ++r) {
                acc[r][0] = fmaf(xv[r], wv.x, acc[r][0]);
                acc[r][1] = fmaf(xv[r], wv.y, acc[r][1]);
                acc[r][2] = fmaf(xv[r], wv.z, acc[r][2]);
                acc[r][3] = fmaf(xv[r], wv.w, acc[r][3]);
            }
        }
        __syncthreads();
    }

    float a_s[4], a_d[4];
    #pragma unroll
    for (int c = 0; c < 4; ++c) { a_s[c] = a_src[tx * 4 + c]; a_d[c] = a_dst[tx * 4 + c]; }

    #pragma unroll
    for (int r = 0; r < 4; ++r) {
        int row = row0 + ty * 4 + r;
        float s = 0.f, d = 0.f;
        #pragma unroll
        for (int c = 0; c < 4; ++c) { s = fmaf(acc[r][c], a_s[c], s); d = fmaf(acc[r][c], a_d[c], d); }
        #pragma unroll
        for (int off = 8; off; off >>= 1) {
            s += __shfl_xor_sync(0xffffffffu, s, off, 16);
            d += __shfl_xor_sync(0xffffffffu, d, off, 16);
        }
        if (row < NN) {
            *(float4*)(g_h + (size_t)row * 64 + tx * 4) =
                make_float4(acc[r][0], acc[r][1], acc[r][2], acc[r][3]);
            if (tx == 0) { g_as[row] = s; g_ad[row] = d; }
        }
    }
}

// ---------------- single-pass online-softmax aggregation ----------------
// One warp per destination node; lane owns features {2*lane, 2*lane+1}.
// j-loop unrolled x4 with independent loads (inactive lanes carry s=0,wgt=0
// so over-reading up to 3 edges gathers row 0 with weight 0 — harmless).
template <bool WRITE_ACT>
__global__ __launch_bounds__(256)
void k_agg(const float* __restrict__ bias, float* __restrict__ OUText, int do_relu) {
    int w = (blockIdx.x * blockDim.x + threadIdx.x) >> 5;
    int lane = threadIdx.x & 31;
    if (w >= NN) return;

    float* OUT = WRITE_ACT ? (float*)g_act : OUText;

    int beg = g_rowptr[w], end = g_rowptr[w + 1];
    float adv = g_ad[w];

    float m = -1e30f;
    float acc0 = 0.f, acc1 = 0.f, denom = 0.f;

    for (int base = beg; base < end; base += 32) {
        int i = base + lane;
        float e = -1e30f;
        int s = 0;
        if (i < end) {
            s = g_srcidx[i];
            float t = g_as[s] + adv;
            e = (t > 0.f) ? t : NEG_SLOPE * t;
        }
        float bm = e;
        #pragma unroll
        for (int off = 16; off; off >>= 1)
            bm = fmaxf(bm, __shfl_xor_sync(0xffffffffu, bm, off));
        float mnew = fmaxf(m, bm);
        float scale = __expf(m - mnew);
        acc0 *= scale; acc1 *= scale; denom *= scale;
        m = mnew;

        float wgt = (i < end) ? __expf(e - mnew) : 0.f;
        denom += wgt;

        int cnt = end - base; if (cnt > 32) cnt = 32;
        int cnt4 = (cnt + 3) & ~3;
        for (int j = 0; j < cnt4; j += 4) {
            float wj0 = __shfl_sync(0xffffffffu, wgt, j);
            float wj1 = __shfl_sync(0xffffffffu, wgt, j + 1);
            float wj2 = __shfl_sync(0xffffffffu, wgt, j + 2);
            float wj3 = __shfl_sync(0xffffffffu, wgt, j + 3);
            int sj0 = __shfl_sync(0xffffffffu, s, j);
            int sj1 = __shfl_sync(0xffffffffu, s, j + 1);
            int sj2 = __shfl_sync(0xffffffffu, s, j + 2);
            int sj3 = __shfl_sync(0xffffffffu, s, j + 3);
            float2 v0 = *(const float2*)(g_h + (size_t)sj0 * 64 + 2 * lane);
            float2 v1 = *(const float2*)(g_h + (size_t)sj1 * 64 + 2 * lane);
            float2 v2 = *(const float2*)(g_h + (size_t)sj2 * 64 + 2 * lane);
            float2 v3 = *(const float2*)(g_h + (size_t)sj3 * 64 + 2 * lane);
            acc0 = fmaf(wj0, v0.x, acc0); acc1 = fmaf(wj0, v0.y, acc1);
            acc0 = fmaf(wj1, v1.x, acc0); acc1 = fmaf(wj1, v1.y, acc1);
            acc0 = fmaf(wj2, v2.x, acc0); acc1 = fmaf(wj2, v2.y, acc1);
            acc0 = fmaf(wj3, v3.x, acc0); acc1 = fmaf(wj3, v3.y, acc1);
        }
    }
    #pragma unroll
    for (int off = 16; off; off >>= 1)
        denom += __shfl_xor_sync(0xffffffffu, denom, off);

    float inv = 1.f / denom;   // self-loop guarantees non-empty segment
    float o0 = fmaf(acc0, inv, bias[2 * lane]);
    float o1 = fmaf(acc1, inv, bias[2 * lane + 1]);
    if (do_relu) { o0 = fmaxf(o0, 0.f); o1 = fmaxf(o1, 0.f); }
    *(float2*)(OUT + (size_t)w * 64 + 2 * lane) = make_float2(o0, o1);
}

// ---------------- launch ----------------
extern "C" void kernel_launch(void* const* d_in, const int* in_sizes, int n_in,
                              void* d_out, int out_size) {
    const float* x   = (const float*)d_in[0];
    const void*  ei  = d_in[1];                 // int32 or int64 — detected on device
    const float* W1  = (const float*)d_in[2];
    const float* a1s = (const float*)d_in[3];
    const float* a1d = (const float*)d_in[4];
    const float* b1  = (const float*)d_in[5];
    const float* W2  = (const float*)d_in[6];
    const float* a2s = (const float*)d_in[7];
    const float* a2d = (const float*)d_in[8];
    const float* b2  = (const float*)d_in[9];
    float* out = (float*)d_out;

    const int SCAN_BLOCKS = (NN + 511) / 512;   // 98
    const int WARP_GRID   = (NN * 32 + 255) / 256;

    // init+detect, then CSR build (dst-sorted)
    k_init   <<<197, 256>>>((const int*)ei);
    k_hist   <<<(TEg + 255) / 256, 256>>>(ei);
    k_scan1  <<<SCAN_BLOCKS, 512>>>();
    k_scan3  <<<(NN + 255) / 256, 256>>>(SCAN_BLOCKS);
    k_scatter<<<(TEg + 255) / 256, 256>>>(ei);

    // layer 1
    k_gemm<128, false><<<(NN + 63) / 64, 256>>>(x, W1, a1s, a1d);
    k_agg<true>        <<<WARP_GRID, 256>>>(b1, out /*unused*/, 1);

    // layer 2
    k_gemm<64, true>   <<<(NN + 63) / 64, 256>>>(x /*unused*/, W2, a2s, a2d);
    k_agg<false>       <<<WARP_GRID, 256>>>(b2, out, 0);
}

// round 9
// speedup vs baseline: 1.0505x; 1.0505x over previous
#include <cuda_runtime.h>

#define NN 50000
#define EE 800000
#define TEg (EE + NN)          // edges + self loops
#define NEG_SLOPE 0.2f
#define SCAT_BLOCKS ((TEg + 255) / 256)   // 3321
#define GEMM_BLOCKS ((NN + 63) / 64)      // 782

// -------- static device scratch (no allocations allowed) --------
// NOTE: g_cnt relies on the zero-at-start invariant: statically zero-initialized,
// and k_scan1 re-zeroes it after consuming, so every run (incl. graph replays)
// sees g_cnt == 0 on entry.
__device__ __align__(16) float g_h[NN * 64];     // GEMM output (h of current layer)
__device__ __align__(16) float g_act[NN * 64];   // layer-1 activated output
__device__ float g_as[NN];
__device__ float g_ad[NN];
__device__ int   g_cnt[NN];
__device__ int   g_rowptr[NN + 1];
__device__ int   g_cursor[NN];
__device__ int   g_srcidx[TEg];
__device__ int   g_bsums[128];

// Per-block dtype self-detection: sample the first 256 odd 32-bit words.
// int64 indices < 50000 -> high halves all zero; int32 -> random nonzero.
// Same data => same verdict in every block. Costs 1 LDG + 1 syncthreads_or.
__device__ __forceinline__ bool detect_is64(const int* e32) {
    int any = __syncthreads_or(e32[2 * threadIdx.x + 1]);
    return any == 0;
}

// ---------------- CSR build ----------------
__global__ __launch_bounds__(256) void k_hist(const void* __restrict__ ei) {
    const int* e32 = (const int*)ei;
    bool is64 = detect_is64(e32);
    int i = blockIdx.x * 256 + threadIdx.x;
    if (i >= TEg) return;
    int d;
    if (i < EE)
        d = is64 ? (int)((const long long*)ei)[(long long)EE + i] : e32[EE + i];
    else
        d = i - EE;
    if ((unsigned)d < NN) atomicAdd(&g_cnt[d], 1);
}

// block-level inclusive scan (shfl-based), 512 threads; zeroes g_cnt after read
__global__ void k_scan1() {
    __shared__ int wsum[16];
    int t = threadIdx.x;
    int lane = t & 31, wid = t >> 5;
    int i = blockIdx.x * 512 + t;
    int v = 0;
    if (i < NN) { v = g_cnt[i]; g_cnt[i] = 0; }   // restore zero-invariant

    int s = v;
    #pragma unroll
    for (int off = 1; off < 32; off <<= 1) {
        int n = __shfl_up_sync(0xffffffffu, s, off);
        if (lane >= off) s += n;
    }
    if (lane == 31) wsum[wid] = s;
    __syncthreads();
    if (wid == 0) {
        int ws = (lane < 16) ? wsum[lane] : 0;
        #pragma unroll
        for (int off = 1; off < 16; off <<= 1) {
            int n = __shfl_up_sync(0xffffffffu, ws, off);
            if (lane >= off) ws += n;
        }
        if (lane < 16) wsum[lane] = ws;
    }
    __syncthreads();
    int base = (wid > 0) ? wsum[wid - 1] : 0;
    s += base;
    if (i < NN) g_rowptr[i + 1] = s;
    if (t == 511) g_bsums[blockIdx.x] = s;
}

// add block offsets; each block redundantly scans the 98 block sums (parallel)
__global__ __launch_bounds__(256) void k_scan3(int nblocks) {
    __shared__ int boff[128];
    __shared__ int wtot[4];
    int t = threadIdx.x;
    if (t < 128) {
        int lane = t & 31, wd = t >> 5;
        int v = (t < nblocks) ? g_bsums[t] : 0;
        int s = v;
        #pragma unroll
        for (int off = 1; off < 32; off <<= 1) {
            int n = __shfl_up_sync(0xffffffffu, s, off);
            if (lane >= off) s += n;
        }
        boff[t] = s;
        if (lane == 31) wtot[wd] = s;
    }
    __syncthreads();
    if (t < 128) {
        int wd = t >> 5;
        int add = 0;
        #pragma unroll
        for (int j = 0; j < 3; ++j)
            if (j < wd) add += wtot[j];
        boff[t] += add;
    }
    __syncthreads();
    int i = blockIdx.x * 256 + t;
    if (i == 0) { g_rowptr[0] = 0; g_cursor[0] = 0; }
    if (i < NN) {
        int blk = i >> 9;
        int off = (blk > 0) ? boff[blk - 1] : 0;
        int v = g_rowptr[i + 1] + off;
        g_rowptr[i + 1] = v;
        if (i + 1 < NN) g_cursor[i + 1] = v;
    }
}

// ---------------- GEMM tile body (shared by standalone + fused kernels) ----
// H[N,64] = X[N,FIN] @ W[FIN,64];  g_as[n] = H[n]·a_src;  g_ad[n] = H[n]·a_dst
template <int FIN, bool USE_ACT>
__device__ __forceinline__
void gemm_tile(int bid, const float* __restrict__ Xext, const float* __restrict__ W,
               const float* __restrict__ a_src, const float* __restrict__ a_dst) {
    __shared__ float Xs[64][36];
    __shared__ float Ws[32][68];

    const float* X = USE_ACT ? (const float*)g_act : Xext;

    int tid = threadIdx.x;
    int tx = tid & 15, ty = tid >> 4;
    int row0 = bid * 64;

    float acc[4][4] = {};

    for (int k0 = 0; k0 < FIN; k0 += 32) {
        #pragma unroll
        for (int l = 0; l < 2; ++l) {
            int idx = l * 256 + tid;
            int r = idx >> 3, kk4 = idx & 7;
            int row = row0 + r;
            float4 v = make_float4(0.f, 0.f, 0.f, 0.f);
            if (row < NN) v = *(const float4*)(X + (size_t)row * FIN + k0 + kk4 * 4);
            *(float4*)(&Xs[r][kk4 * 4]) = v;
        }
        #pragma unroll
        for (int l = 0; l < 2; ++l) {
            int idx = l * 256 + tid;
            int k = idx >> 4, c4 = idx & 15;
            float4 v = *(const float4*)(W + (size_t)(k0 + k) * 64 + c4 * 4);
            *(float4*)(&Ws[k][c4 * 4]) = v;
        }
        __syncthreads();

        #pragma unroll
        for (int kk = 0; kk < 32; ++kk) {
            float4 wv = *(const float4*)(&Ws[kk][tx * 4]);
            float xv[4];
            #pragma unroll
            for (int r = 0; r < 4; ++r) xv[r] = Xs[ty * 4 + r][kk];
            #pragma unroll
            for (int r = 0; r < 4; ++r) {
                acc[r][0] = fmaf(xv[r], wv.x, acc[r][0]);
                acc[r][1] = fmaf(xv[r], wv.y, acc[r][1]);
                acc[r][2] = fmaf(xv[r], wv.z, acc[r][2]);
                acc[r][3] = fmaf(xv[r], wv.w, acc[r][3]);
            }
        }
        __syncthreads();
    }

    float a_s[4], a_d[4];
    #pragma unroll
    for (int c = 0; c < 4; ++c) { a_s[c] = a_src[tx * 4 + c]; a_d[c] = a_dst[tx * 4 + c]; }

    #pragma unroll
    for (int r = 0; r < 4; ++r) {
        int row = row0 + ty * 4 + r;
        float s = 0.f, d = 0.f;
        #pragma unroll
        for (int c = 0; c < 4; ++c) { s = fmaf(acc[r][c], a_s[c], s); d = fmaf(acc[r][c], a_d[c], d); }
        #pragma unroll
        for (int off = 8; off; off >>= 1) {
            s += __shfl_xor_sync(0xffffffffu, s, off, 16);
            d += __shfl_xor_sync(0xffffffffu, d, off, 16);
        }
        if (row < NN) {
            *(float4*)(g_h + (size_t)row * 64 + tx * 4) =
                make_float4(acc[r][0], acc[r][1], acc[r][2], acc[r][3]);
            if (tx == 0) { g_as[row] = s; g_ad[row] = d; }
        }
    }
}

// Fused layer-1 launch: scatter blocks first (start immediately), then gemm tiles.
__global__ __launch_bounds__(256)
void k_fused1(const float* __restrict__ X, const float* __restrict__ W,
              const float* __restrict__ a_src, const float* __restrict__ a_dst,
              const void* __restrict__ ei) {
    if ((int)blockIdx.x < SCAT_BLOCKS) {
        const int* e32 = (const int*)ei;
        bool is64 = detect_is64(e32);
        int i = blockIdx.x * 256 + threadIdx.x;
        if (i >= TEg) return;
        int s, d;
        if (i < EE) {
            if (is64) {
                s = (int)((const long long*)ei)[i];
                d = (int)((const long long*)ei)[(long long)EE + i];
            } else {
                s = e32[i];
                d = e32[EE + i];
            }
        } else { s = i - EE; d = s; }
        if ((unsigned)d >= NN || (unsigned)s >= NN) return;
        int pos = atomicAdd(&g_cursor[d], 1);
        if ((unsigned)pos < TEg) g_srcidx[pos] = s;
        return;
    }
    gemm_tile<128, false>(blockIdx.x - SCAT_BLOCKS, X, W, a_src, a_dst);
}

template <int FIN, bool USE_ACT>
__global__ __launch_bounds__(256)
void k_gemm(const float* __restrict__ X, const float* __restrict__ W,
            const float* __restrict__ a_src, const float* __restrict__ a_dst) {
    gemm_tile<FIN, USE_ACT>(blockIdx.x, X, W, a_src, a_dst);
}

// ---------------- single-pass online-softmax aggregation ----------------
// One warp per destination node; lane owns features {2*lane, 2*lane+1}.
template <bool WRITE_ACT>
__global__ __launch_bounds__(256)
void k_agg(const float* __restrict__ bias, float* __restrict__ OUText, int do_relu) {
    int w = (blockIdx.x * blockDim.x + threadIdx.x) >> 5;
    int lane = threadIdx.x & 31;
    if (w >= NN) return;

    float* OUT = WRITE_ACT ? (float*)g_act : OUText;

    int beg = g_rowptr[w], end = g_rowptr[w + 1];
    float adv = g_ad[w];

    float m = -1e30f;
    float acc0 = 0.f, acc1 = 0.f, denom = 0.f;

    for (int base = beg; base < end; base += 32) {
        int i = base + lane;
        float e = -1e30f;
        int s = 0;
        if (i < end) {
            s = g_srcidx[i];
            float t = g_as[s] + adv;
            e = (t > 0.f) ? t : NEG_SLOPE * t;
        }
        float bm = e;
        #pragma unroll
        for (int off = 16; off; off >>= 1)
            bm = fmaxf(bm, __shfl_xor_sync(0xffffffffu, bm, off));
        float mnew = fmaxf(m, bm);
        float scale = __expf(m - mnew);
        acc0 *= scale; acc1 *= scale; denom *= scale;
        m = mnew;

        float wgt = (i < end) ? __expf(e - mnew) : 0.f;
        denom += wgt;

        int cnt = end - base; if (cnt > 32) cnt = 32;
        int cnt4 = (cnt + 3) & ~3;
        for (int j = 0; j < cnt4; j += 4) {
            float wj0 = __shfl_sync(0xffffffffu, wgt, j);
            float wj1 = __shfl_sync(0xffffffffu, wgt, j + 1);
            float wj2 = __shfl_sync(0xffffffffu, wgt, j + 2);
            float wj3 = __shfl_sync(0xffffffffu, wgt, j + 3);
            int sj0 = __shfl_sync(0xffffffffu, s, j);
            int sj1 = __shfl_sync(0xffffffffu, s, j + 1);
            int sj2 = __shfl_sync(0xffffffffu, s, j + 2);
            int sj3 = __shfl_sync(0xffffffffu, s, j + 3);
            float2 v0 = *(const float2*)(g_h + (size_t)sj0 * 64 + 2 * lane);
            float2 v1 = *(const float2*)(g_h + (size_t)sj1 * 64 + 2 * lane);
            float2 v2 = *(const float2*)(g_h + (size_t)sj2 * 64 + 2 * lane);
            float2 v3 = *(const float2*)(g_h + (size_t)sj3 * 64 + 2 * lane);
            acc0 = fmaf(wj0, v0.x, acc0); acc1 = fmaf(wj0, v0.y, acc1);
            acc0 = fmaf(wj1, v1.x, acc0); acc1 = fmaf(wj1, v1.y, acc1);
            acc0 = fmaf(wj2, v2.x, acc0); acc1 = fmaf(wj2, v2.y, acc1);
            acc0 = fmaf(wj3, v3.x, acc0); acc1 = fmaf(wj3, v3.y, acc1);
        }
    }
    #pragma unroll
    for (int off = 16; off; off >>= 1)
        denom += __shfl_xor_sync(0xffffffffu, denom, off);

    float inv = 1.f / denom;   // self-loop guarantees non-empty segment
    float o0 = fmaf(acc0, inv, bias[2 * lane]);
    float o1 = fmaf(acc1, inv, bias[2 * lane + 1]);
    if (do_relu) { o0 = fmaxf(o0, 0.f); o1 = fmaxf(o1, 0.f); }
    *(float2*)(OUT + (size_t)w * 64 + 2 * lane) = make_float2(o0, o1);
}

// ---------------- launch ----------------
extern "C" void kernel_launch(void* const* d_in, const int* in_sizes, int n_in,
                              void* d_out, int out_size) {
    const float* x   = (const float*)d_in[0];
    const void*  ei  = d_in[1];                 // int32 or int64 — self-detected
    const float* W1  = (const float*)d_in[2];
    const float* a1s = (const float*)d_in[3];
    const float* a1d = (const float*)d_in[4];
    const float* b1  = (const float*)d_in[5];
    const float* W2  = (const float*)d_in[6];
    const float* a2s = (const float*)d_in[7];
    const float* a2d = (const float*)d_in[8];
    const float* b2  = (const float*)d_in[9];
    float* out = (float*)d_out;

    const int SCAN_BLOCKS = (NN + 511) / 512;   // 98
    const int WARP_GRID   = (NN * 32 + 255) / 256;

    // CSR prefix chain (g_cnt is zero on entry by invariant)
    k_hist  <<<SCAT_BLOCKS, 256>>>(ei);
    k_scan1 <<<SCAN_BLOCKS, 512>>>();
    k_scan3 <<<(NN + 255) / 256, 256>>>(SCAN_BLOCKS);

    // layer 1: scatter (CSR finalize) fused with GEMM1
    k_fused1<<<SCAT_BLOCKS + GEMM_BLOCKS, 256>>>(x, W1, a1s, a1d, ei);
    k_agg<true> <<<WARP_GRID, 256>>>(b1, out /*unused*/, 1);

    // layer 2
    k_gemm<64, true><<<GEMM_BLOCKS, 256>>>(x /*unused*/, W2, a2s, a2d);
    k_agg<false>    <<<WARP_GRID, 256>>>(b2, out, 0);
}

// round 10
// speedup vs baseline: 1.1309x; 1.0765x over previous
#include <cuda_runtime.h>

#define NN 50000
#define EE 800000
#define TEg (EE + NN)          // edges + self loops
#define NEG_SLOPE 0.2f
#define SCAT_BLOCKS ((TEg + 255) / 256)   // 3321
#define GEMM_BLOCKS ((NN + 127) / 128)    // 391 (tensor-core tiles, 128 rows)
#define WSPLIT_BLOCKS 48                  // (128*64 + 64*64) / 256

// -------- static device scratch (no allocations allowed) --------
// g_cnt zero-at-start invariant: statically zeroed; k_scan1 re-zeroes after read.
__device__ __align__(16) float g_h[NN * 64];
__device__ __align__(16) float g_act[NN * 64];
__device__ float g_as[NN];
__device__ float g_ad[NN];
__device__ int   g_cnt[NN];
__device__ int   g_rowptr[NN + 1];
__device__ int   g_cursor[NN];
__device__ int   g_srcidx[TEg];
__device__ int   g_bsums[128];
__device__ __align__(16) unsigned g_w1h[128 * 64];
__device__ __align__(16) unsigned g_w1l[128 * 64];
__device__ __align__(16) unsigned g_w2h[64 * 64];
__device__ __align__(16) unsigned g_w2l[64 * 64];

// tf32 split: x = hi + lo, both tf32-representable (bits are fp32-compatible)
__device__ __forceinline__ void split_tf32(float x, unsigned& hi, unsigned& lo) {
    asm("cvt.rna.tf32.f32 %0, %1;" : "=r"(hi) : "f"(x));
    float r = x - __uint_as_float(hi);
    asm("cvt.rna.tf32.f32 %0, %1;" : "=r"(lo) : "f"(r));
}

__device__ __forceinline__ void mma_tf32(float c[4], const unsigned a[4], const unsigned b[2]) {
    asm volatile(
        "mma.sync.aligned.m16n8k8.row.col.f32.tf32.tf32.f32 "
        "{%0,%1,%2,%3}, {%4,%5,%6,%7}, {%8,%9}, {%0,%1,%2,%3};"
        : "+f"(c[0]), "+f"(c[1]), "+f"(c[2]), "+f"(c[3])
        : "r"(a[0]), "r"(a[1]), "r"(a[2]), "r"(a[3]), "r"(b[0]), "r"(b[1]));
}

// Per-block dtype self-detection (int64 high halves of indices < 50000 are 0)
__device__ __forceinline__ bool detect_is64(const int* e32) {
    int any = __syncthreads_or(e32[2 * threadIdx.x + 1]);
    return any == 0;
}

// ---------------- CSR hist + (fused) weight splitting ----------------
__global__ __launch_bounds__(256)
void k_hist(const void* __restrict__ ei, const float* __restrict__ W1,
            const float* __restrict__ W2) {
    if ((int)blockIdx.x >= SCAT_BLOCKS) {
        int idx = ((int)blockIdx.x - SCAT_BLOCKS) * 256 + threadIdx.x;
        if (idx < 128 * 64) {
            unsigned h, l; split_tf32(W1[idx], h, l);
            g_w1h[idx] = h; g_w1l[idx] = l;
        } else {
            int j = idx - 128 * 64;   // < 64*64
            unsigned h, l; split_tf32(W2[j], h, l);
            g_w2h[j] = h; g_w2l[j] = l;
        }
        return;
    }
    const int* e32 = (const int*)ei;
    bool is64 = detect_is64(e32);
    int i = blockIdx.x * 256 + threadIdx.x;
    if (i >= TEg) return;
    int d;
    if (i < EE)
        d = is64 ? (int)((const long long*)ei)[(long long)EE + i] : e32[EE + i];
    else
        d = i - EE;
    if ((unsigned)d < NN) atomicAdd(&g_cnt[d], 1);
}

// block-level inclusive scan (shfl-based); zeroes g_cnt after read
__global__ void k_scan1() {
    __shared__ int wsum[16];
    int t = threadIdx.x;
    int lane = t & 31, wid = t >> 5;
    int i = blockIdx.x * 512 + t;
    int v = 0;
    if (i < NN) { v = g_cnt[i]; g_cnt[i] = 0; }

    int s = v;
    #pragma unroll
    for (int off = 1; off < 32; off <<= 1) {
        int n = __shfl_up_sync(0xffffffffu, s, off);
        if (lane >= off) s += n;
    }
    if (lane == 31) wsum[wid] = s;
    __syncthreads();
    if (wid == 0) {
        int ws = (lane < 16) ? wsum[lane] : 0;
        #pragma unroll
        for (int off = 1; off < 16; off <<= 1) {
            int n = __shfl_up_sync(0xffffffffu, ws, off);
            if (lane >= off) ws += n;
        }
        if (lane < 16) wsum[lane] = ws;
    }
    __syncthreads();
    int base = (wid > 0) ? wsum[wid - 1] : 0;
    s += base;
    if (i < NN) g_rowptr[i + 1] = s;
    if (t == 511) g_bsums[blockIdx.x] = s;
}

__global__ __launch_bounds__(256) void k_scan3(int nblocks) {
    __shared__ int boff[128];
    __shared__ int wtot[4];
    int t = threadIdx.x;
    if (t < 128) {
        int lane = t & 31, wd = t >> 5;
        int v = (t < nblocks) ? g_bsums[t] : 0;
        int s = v;
        #pragma unroll
        for (int off = 1; off < 32; off <<= 1) {
            int n = __shfl_up_sync(0xffffffffu, s, off);
            if (lane >= off) s += n;
        }
        boff[t] = s;
        if (lane == 31) wtot[wd] = s;
    }
    __syncthreads();
    if (t < 128) {
        int wd = t >> 5;
        int add = 0;
        #pragma unroll
        for (int j = 0; j < 3; ++j)
            if (j < wd) add += wtot[j];
        boff[t] += add;
    }
    __syncthreads();
    int i = blockIdx.x * 256 + t;
    if (i == 0) { g_rowptr[0] = 0; g_cursor[0] = 0; }
    if (i < NN) {
        int blk = i >> 9;
        int off = (blk > 0) ? boff[blk - 1] : 0;
        int v = g_rowptr[i + 1] + off;
        g_rowptr[i + 1] = v;
        if (i + 1 < NN) g_cursor[i + 1] = v;
    }
}

// ---------------- tensor-core GEMM tile (3xTF32 compensated) ----------------
// H[N,64] = X[N,FIN] @ W[FIN,64]; also g_as/g_ad projections.
// Block 256 thr = 8 warps (4 M x 2 N); block tile 128x64; warp tile 32x32.
template <int FIN, bool USE_ACT, bool LAYER1>
__device__ __forceinline__
void gemm_tc(int bid, const float* __restrict__ Xext,
             const float* __restrict__ a_src, const float* __restrict__ a_dst) {
    __shared__ unsigned Ah[128][20], Al[128][20];   // pad 20: conflict-free frags
    __shared__ unsigned Bh[16][72],  Bl[16][72];    // pad 72
    __shared__ float sp_s[2][128], sp_d[2][128];

    const float* X = USE_ACT ? (const float*)g_act : Xext;
    const unsigned* WhG = LAYER1 ? g_w1h : g_w2h;
    const unsigned* WlG = LAYER1 ? g_w1l : g_w2l;

    int tid = threadIdx.x;
    int lane = tid & 31, wid = tid >> 5;
    int wm = wid >> 1, wn = wid & 1;
    int g = lane >> 2, tig = lane & 3;
    int row0 = bid * 128;

    float acc[2][4][4] = {};

    for (int k0 = 0; k0 < FIN; k0 += 16) {
        // A chunk 128x16: 512 float4, 2/thread; split to tf32 hi/lo
        #pragma unroll
        for (int l = 0; l < 2; ++l) {
            int idx = l * 256 + tid;
            int r = idx >> 2, kq = idx & 3;
            int row = row0 + r;
            float4 v = make_float4(0.f, 0.f, 0.f, 0.f);
            if (row < NN) v = *(const float4*)(X + (size_t)row * FIN + k0 + kq * 4);
            unsigned h, lo;
            split_tf32(v.x, h, lo); Ah[r][kq * 4 + 0] = h; Al[r][kq * 4 + 0] = lo;
            split_tf32(v.y, h, lo); Ah[r][kq * 4 + 1] = h; Al[r][kq * 4 + 1] = lo;
            split_tf32(v.z, h, lo); Ah[r][kq * 4 + 2] = h; Al[r][kq * 4 + 2] = lo;
            split_tf32(v.w, h, lo); Ah[r][kq * 4 + 3] = h; Al[r][kq * 4 + 3] = lo;
        }
        // B chunk 16x64 (pre-split): 256 float4 per tile, 1/thread each
        {
            int kr = tid >> 4, c4 = tid & 15;
            const float4 vh = *(const float4*)((const float*)WhG + (size_t)(k0 + kr) * 64 + c4 * 4);
            const float4 vl = *(const float4*)((const float*)WlG + (size_t)(k0 + kr) * 64 + c4 * 4);
            Bh[kr][c4 * 4 + 0] = __float_as_uint(vh.x);
            Bh[kr][c4 * 4 + 1] = __float_as_uint(vh.y);
            Bh[kr][c4 * 4 + 2] = __float_as_uint(vh.z);
            Bh[kr][c4 * 4 + 3] = __float_as_uint(vh.w);
            Bl[kr][c4 * 4 + 0] = __float_as_uint(vl.x);
            Bl[kr][c4 * 4 + 1] = __float_as_uint(vl.y);
            Bl[kr][c4 * 4 + 2] = __float_as_uint(vl.z);
            Bl[kr][c4 * 4 + 3] = __float_as_uint(vl.w);
        }
        __syncthreads();

        #pragma unroll
        for (int ks = 0; ks < 2; ++ks) {
            unsigned bh[4][2], bl[4][2];
            #pragma unroll
            for (int nt = 0; nt < 4; ++nt) {
                int c = wn * 32 + nt * 8 + g;
                bh[nt][0] = Bh[ks * 8 + tig][c];     bh[nt][1] = Bh[ks * 8 + tig + 4][c];
                bl[nt][0] = Bl[ks * 8 + tig][c];     bl[nt][1] = Bl[ks * 8 + tig + 4][c];
            }
            #pragma unroll
            for (int mt = 0; mt < 2; ++mt) {
                int rb = wm * 32 + mt * 16;
                unsigned ah[4], al[4];
                ah[0] = Ah[rb + g][ks * 8 + tig];       ah[1] = Ah[rb + g + 8][ks * 8 + tig];
                ah[2] = Ah[rb + g][ks * 8 + tig + 4];   ah[3] = Ah[rb + g + 8][ks * 8 + tig + 4];
                al[0] = Al[rb + g][ks * 8 + tig];       al[1] = Al[rb + g + 8][ks * 8 + tig];
                al[2] = Al[rb + g][ks * 8 + tig + 4];   al[3] = Al[rb + g + 8][ks * 8 + tig + 4];
                #pragma unroll
                for (int nt = 0; nt < 4; ++nt) {
                    mma_tf32(acc[mt][nt], ah, bh[nt]);
                    mma_tf32(acc[mt][nt], ah, bl[nt]);
                    mma_tf32(acc[mt][nt], al, bh[nt]);
                }
            }
        }
        __syncthreads();
    }

    // H store from C fragments (row-pair per frag, float2 per store)
    #pragma unroll
    for (int mt = 0; mt < 2; ++mt)
        #pragma unroll
        for (int nt = 0; nt < 4; ++nt) {
            int r = row0 + wm * 32 + mt * 16 + g;
            int c = wn * 32 + nt * 8 + 2 * tig;
            if (r < NN)
                *(float2*)(g_h + (size_t)r * 64 + c) = make_float2(acc[mt][nt][0], acc[mt][nt][1]);
            if (r + 8 < NN)
                *(float2*)(g_h + (size_t)(r + 8) * 64 + c) = make_float2(acc[mt][nt][2], acc[mt][nt][3]);
        }

    // attention projections: per-row dot with a_src / a_dst
    float asv[4][2], adv[4][2];
    #pragma unroll
    for (int nt = 0; nt < 4; ++nt) {
        int c = wn * 32 + nt * 8 + 2 * tig;
        asv[nt][0] = a_src[c]; asv[nt][1] = a_src[c + 1];
        adv[nt][0] = a_dst[c]; adv[nt][1] = a_dst[c + 1];
    }
    #pragma unroll
    for (int mt = 0; mt < 2; ++mt) {
        float s0 = 0.f, s1 = 0.f, d0 = 0.f, d1 = 0.f;
        #pragma unroll
        for (int nt = 0; nt < 4; ++nt) {
            s0 = fmaf(acc[mt][nt][0], asv[nt][0], fmaf(acc[mt][nt][1], asv[nt][1], s0));
            s1 = fmaf(acc[mt][nt][2], asv[nt][0], fmaf(acc[mt][nt][3], asv[nt][1], s1));
            d0 = fmaf(acc[mt][nt][0], adv[nt][0], fmaf(acc[mt][nt][1], adv[nt][1], d0));
            d1 = fmaf(acc[mt][nt][2], adv[nt][0], fmaf(acc[mt][nt][3], adv[nt][1], d1));
        }
        s0 += __shfl_xor_sync(0xffffffffu, s0, 1); s0 += __shfl_xor_sync(0xffffffffu, s0, 2);
        s1 += __shfl_xor_sync(0xffffffffu, s1, 1); s1 += __shfl_xor_sync(0xffffffffu, s1, 2);
        d0 += __shfl_xor_sync(0xffffffffu, d0, 1); d0 += __shfl_xor_sync(0xffffffffu, d0, 2);
        d1 += __shfl_xor_sync(0xffffffffu, d1, 1); d1 += __shfl_xor_sync(0xffffffffu, d1, 2);
        if (tig == 0) {
            int rl = wm * 32 + mt * 16 + g;
            sp_s[wn][rl] = s0; sp_s[wn][rl + 8] = s1;
            sp_d[wn][rl] = d0; sp_d[wn][rl + 8] = d1;
        }
    }
    __syncthreads();
    if (tid < 128) {
        int r = row0 + tid;
        if (r < NN) {
            g_as[r] = sp_s[0][tid] + sp_s[1][tid];
            g_ad[r] = sp_d[0][tid] + sp_d[1][tid];
        }
    }
}

// Fused layer-1: gemm blocks first (start heavy work immediately), then scatter.
__global__ __launch_bounds__(256)
void k_fused1(const float* __restrict__ X,
              const float* __restrict__ a_src, const float* __restrict__ a_dst,
              const void* __restrict__ ei) {
    if ((int)blockIdx.x < GEMM_BLOCKS) {
        gemm_tc<128, false, true>(blockIdx.x, X, a_src, a_dst);
        return;
    }
    const int* e32 = (const int*)ei;
    bool is64 = detect_is64(e32);
    int i = ((int)blockIdx.x - GEMM_BLOCKS) * 256 + threadIdx.x;
    if (i >= TEg) return;
    int s, d;
    if (i < EE) {
        if (is64) {
            s = (int)((const long long*)ei)[i];
            d = (int)((const long long*)ei)[(long long)EE + i];
        } else {
            s = e32[i];
            d = e32[EE + i];
        }
    } else { s = i - EE; d = s; }
    if ((unsigned)d >= NN || (unsigned)s >= NN) return;
    int pos = atomicAdd(&g_cursor[d], 1);
    if ((unsigned)pos < TEg) g_srcidx[pos] = s;
}

__global__ __launch_bounds__(256)
void k_gemm2(const float* __restrict__ a_src, const float* __restrict__ a_dst) {
    gemm_tc<64, true, false>(blockIdx.x, nullptr, a_src, a_dst);
}

// ---------------- single-pass online-softmax aggregation ----------------
template <bool WRITE_ACT>
__global__ __launch_bounds__(256)
void k_agg(const float* __restrict__ bias, float* __restrict__ OUText, int do_relu) {
    int w = (blockIdx.x * blockDim.x + threadIdx.x) >> 5;
    int lane = threadIdx.x & 31;
    if (w >= NN) return;

    float* OUT = WRITE_ACT ? (float*)g_act : OUText;

    int beg = g_rowptr[w], end = g_rowptr[w + 1];
    float adv = g_ad[w];

    float m = -1e30f;
    float acc0 = 0.f, acc1 = 0.f, denom = 0.f;

    for (int base = beg; base < end; base += 32) {
        int i = base + lane;
        float e = -1e30f;
        int s = 0;
        if (i < end) {
            s = g_srcidx[i];
            float t = g_as[s] + adv;
            e = (t > 0.f) ? t : NEG_SLOPE * t;
        }
        float bm = e;
        #pragma unroll
        for (int off = 16; off; off >>= 1)
            bm = fmaxf(bm, __shfl_xor_sync(0xffffffffu, bm, off));
        float mnew = fmaxf(m, bm);
        float scale = __expf(m - mnew);
        acc0 *= scale; acc1 *= scale; denom *= scale;
        m = mnew;

        float wgt = (i < end) ? __expf(e - mnew) : 0.f;
        denom += wgt;

        int cnt = end - base; if (cnt > 32) cnt = 32;
        int cnt4 = (cnt + 3) & ~3;
        for (int j = 0; j < cnt4; j += 4) {
            float wj0 = __shfl_sync(0xffffffffu, wgt, j);
            float wj1 = __shfl_sync(0xffffffffu, wgt, j + 1);
            float wj2 = __shfl_sync(0xffffffffu, wgt, j + 2);
            float wj3 = __shfl_sync(0xffffffffu, wgt, j + 3);
            int sj0 = __shfl_sync(0xffffffffu, s, j);
            int sj1 = __shfl_sync(0xffffffffu, s, j + 1);
            int sj2 = __shfl_sync(0xffffffffu, s, j + 2);
            int sj3 = __shfl_sync(0xffffffffu, s, j + 3);
            float2 v0 = *(const float2*)(g_h + (size_t)sj0 * 64 + 2 * lane);
            float2 v1 = *(const float2*)(g_h + (size_t)sj1 * 64 + 2 * lane);
            float2 v2 = *(const float2*)(g_h + (size_t)sj2 * 64 + 2 * lane);
            float2 v3 = *(const float2*)(g_h + (size_t)sj3 * 64 + 2 * lane);
            acc0 = fmaf(wj0, v0.x, acc0); acc1 = fmaf(wj0, v0.y, acc1);
            acc0 = fmaf(wj1, v1.x, acc0); acc1 = fmaf(wj1, v1.y, acc1);
            acc0 = fmaf(wj2, v2.x, acc0); acc1 = fmaf(wj2, v2.y, acc1);
            acc0 = fmaf(wj3, v3.x, acc0); acc1 = fmaf(wj3, v3.y, acc1);
        }
    }
    #pragma unroll
    for (int off = 16; off; off >>= 1)
        denom += __shfl_xor_sync(0xffffffffu, denom, off);

    float inv = 1.f / denom;
    float o0 = fmaf(acc0, inv, bias[2 * lane]);
    float o1 = fmaf(acc1, inv, bias[2 * lane + 1]);
    if (do_relu) { o0 = fmaxf(o0, 0.f); o1 = fmaxf(o1, 0.f); }
    *(float2*)(OUT + (size_t)w * 64 + 2 * lane) = make_float2(o0, o1);
}

// ---------------- launch ----------------
extern "C" void kernel_launch(void* const* d_in, const int* in_sizes, int n_in,
                              void* d_out, int out_size) {
    const float* x   = (const float*)d_in[0];
    const void*  ei  = d_in[1];                 // int32 or int64 — self-detected
    const float* W1  = (const float*)d_in[2];
    const float* a1s = (const float*)d_in[3];
    const float* a1d = (const float*)d_in[4];
    const float* b1  = (const float*)d_in[5];
    const float* W2  = (const float*)d_in[6];
    const float* a2s = (const float*)d_in[7];
    const float* a2d = (const float*)d_in[8];
    const float* b2  = (const float*)d_in[9];
    float* out = (float*)d_out;

    const int SCAN_BLOCKS = (NN + 511) / 512;   // 98
    const int WARP_GRID   = (NN * 32 + 255) / 256;

    // hist (+ fused W tf32-split) → scan → scan-combine
    k_hist  <<<SCAT_BLOCKS + WSPLIT_BLOCKS, 256>>>(ei, W1, W2);
    k_scan1 <<<SCAN_BLOCKS, 512>>>();
    k_scan3 <<<(NN + 255) / 256, 256>>>(SCAN_BLOCKS);

    // layer 1: tensor-core GEMM1 fused with CSR scatter
    k_fused1<<<GEMM_BLOCKS + SCAT_BLOCKS, 256>>>(x, a1s, a1d, ei);
    k_agg<true> <<<WARP_GRID, 256>>>(b1, out /*unused*/, 1);

    // layer 2
    k_gemm2 <<<GEMM_BLOCKS, 256>>>(a2s, a2d);
    k_agg<false><<<WARP_GRID, 256>>>(b2, out, 0);
}

// round 12
// speedup vs baseline: 1.1683x; 1.0331x over previous
#include <cuda_runtime.h>
#include <cuda_fp16.h>

#define NN 50000
#define EE 800000
#define TEg (EE + NN)          // edges + self loops
#define NEG_SLOPE 0.2f
#define SCAT_BLOCKS ((TEg + 255) / 256)   // 3321
#define GEMM_BLOCKS ((NN + 127) / 128)    // 391 (tensor-core tiles, 128 rows)
#define WSPLIT_BLOCKS 48                  // (128*64 + 64*64) / 256

// -------- static device scratch (no allocations allowed) --------
// g_cnt zero-at-start invariant: statically zeroed; k_scan1 re-zeroes after read.
__device__ __align__(16) __half2 g_h16[NN * 32];   // h in fp16 (gather stream)
__device__ __align__(16) float g_act[NN * 64];     // layer-1 activated output (fp32)
__device__ float g_as[NN];
__device__ float g_ad[NN];
__device__ int   g_cnt[NN];
__device__ int   g_rowptr[NN + 1];
__device__ int   g_cursor[NN];
__device__ int   g_srcidx[TEg];
__device__ int   g_bsums[128];
__device__ __align__(16) unsigned g_w1h[128 * 64];
__device__ __align__(16) unsigned g_w1l[128 * 64];
__device__ __align__(16) unsigned g_w2h[64 * 64];
__device__ __align__(16) unsigned g_w2l[64 * 64];

// tf32 split: x = hi + lo, both tf32-representable (bits are fp32-compatible)
__device__ __forceinline__ void split_tf32(float x, unsigned& hi, unsigned& lo) {
    asm("cvt.rna.tf32.f32 %0, %1;" : "=r"(hi) : "f"(x));
    float r = x - __uint_as_float(hi);
    asm("cvt.rna.tf32.f32 %0, %1;" : "=r"(lo) : "f"(r));
}

__device__ __forceinline__ void mma_tf32(float c[4], const unsigned a[4], const unsigned b[2]) {
    asm volatile(
        "mma.sync.aligned.m16n8k8.row.col.f32.tf32.tf32.f32 "
        "{%0,%1,%2,%3}, {%4,%5,%6,%7}, {%8,%9}, {%0,%1,%2,%3};"
        : "+f"(c[0]), "+f"(c[1]), "+f"(c[2]), "+f"(c[3])
        : "r"(a[0]), "r"(a[1]), "r"(a[2]), "r"(a[3]), "r"(b[0]), "r"(b[1]));
}

// Per-block dtype self-detection (int64 high halves of indices < 50000 are 0)
__device__ __forceinline__ bool detect_is64(const int* e32) {
    int any = __syncthreads_or(e32[2 * threadIdx.x + 1]);
    return any == 0;
}

// ---------------- CSR hist + (fused) weight splitting ----------------
__global__ __launch_bounds__(256)
void k_hist(const void* __restrict__ ei, const float* __restrict__ W1,
            const float* __restrict__ W2) {
    if ((int)blockIdx.x >= SCAT_BLOCKS) {
        int idx = ((int)blockIdx.x - SCAT_BLOCKS) * 256 + threadIdx.x;
        if (idx < 128 * 64) {
            unsigned h, l; split_tf32(W1[idx], h, l);
            g_w1h[idx] = h; g_w1l[idx] = l;
        } else {
            int j = idx - 128 * 64;   // < 64*64
            unsigned h, l; split_tf32(W2[j], h, l);
            g_w2h[j] = h; g_w2l[j] = l;
        }
        return;
    }
    const int* e32 = (const int*)ei;
    bool is64 = detect_is64(e32);
    int i = blockIdx.x * 256 + threadIdx.x;
    if (i >= TEg) return;
    int d;
    if (i < EE)
        d = is64 ? (int)((const long long*)ei)[(long long)EE + i] : e32[EE + i];
    else
        d = i - EE;
    if ((unsigned)d < NN) atomicAdd(&g_cnt[d], 1);
}

// block-level inclusive scan (shfl-based); zeroes g_cnt after read
__global__ void k_scan1() {
    __shared__ int wsum[16];
    int t = threadIdx.x;
    int lane = t & 31, wid = t >> 5;
    int i = blockIdx.x * 512 + t;
    int v = 0;
    if (i < NN) { v = g_cnt[i]; g_cnt[i] = 0; }

    int s = v;
    #pragma unroll
    for (int off = 1; off < 32; off <<= 1) {
        int n = __shfl_up_sync(0xffffffffu, s, off);
        if (lane >= off) s += n;
    }
    if (lane == 31) wsum[wid] = s;
    __syncthreads();
    if (wid == 0) {
        int ws = (lane < 16) ? wsum[lane] : 0;
        #pragma unroll
        for (int off = 1; off < 16; off <<= 1) {
            int n = __shfl_up_sync(0xffffffffu, ws, off);
            if (lane >= off) ws += n;
        }
        if (lane < 16) wsum[lane] = ws;
    }
    __syncthreads();
    int base = (wid > 0) ? wsum[wid - 1] : 0;
    s += base;
    if (i < NN) g_rowptr[i + 1] = s;
    if (t == 511) g_bsums[blockIdx.x] = s;
}

__global__ __launch_bounds__(256) void k_scan3(int nblocks) {
    __shared__ int boff[128];
    __shared__ int wtot[4];
    int t = threadIdx.x;
    if (t < 128) {
        int lane = t & 31, wd = t >> 5;
        int v = (t < nblocks) ? g_bsums[t] : 0;
        int s = v;
        #pragma unroll
        for (int off = 1; off < 32; off <<= 1) {
            int n = __shfl_up_sync(0xffffffffu, s, off);
            if (lane >= off) s += n;
        }
        boff[t] = s;
        if (lane == 31) wtot[wd] = s;
    }
    __syncthreads();
    if (t < 128) {
        int wd = t >> 5;
        int add = 0;
        #pragma unroll
        for (int j = 0; j < 3; ++j)
            if (j < wd) add += wtot[j];
        boff[t] += add;
    }
    __syncthreads();
    int i = blockIdx.x * 256 + t;
    if (i == 0) { g_rowptr[0] = 0; g_cursor[0] = 0; }
    if (i < NN) {
        int blk = i >> 9;
        int off = (blk > 0) ? boff[blk - 1] : 0;
        int v = g_rowptr[i + 1] + off;
        g_rowptr[i + 1] = v;
        if (i + 1 < NN) g_cursor[i + 1] = v;
    }
}

// ---------------- tensor-core GEMM tile (3xTF32 compensated) ----------------
// H[N,64] = X[N,FIN] @ W[FIN,64]; H stored fp16; g_as/g_ad from fp32 accs.
// Block 256 thr = 8 warps (4 M x 2 N); block tile 128x64; warp tile 32x32.
template <int FIN, bool USE_ACT, bool LAYER1>
__device__ __forceinline__
void gemm_tc(int bid, const float* __restrict__ Xext,
             const float* __restrict__ a_src, const float* __restrict__ a_dst) {
    __shared__ unsigned Ah[128][20], Al[128][20];
    __shared__ unsigned Bh[16][72],  Bl[16][72];
    __shared__ float sp_s[2][128], sp_d[2][128];

    const float* X = USE_ACT ? (const float*)g_act : Xext;
    const unsigned* WhG = LAYER1 ? g_w1h : g_w2h;
    const unsigned* WlG = LAYER1 ? g_w1l : g_w2l;

    int tid = threadIdx.x;
    int lane = tid & 31, wid = tid >> 5;
    int wm = wid >> 1, wn = wid & 1;
    int g = lane >> 2, tig = lane & 3;
    int row0 = bid * 128;

    float acc[2][4][4] = {};

    for (int k0 = 0; k0 < FIN; k0 += 16) {
        #pragma unroll
        for (int l = 0; l < 2; ++l) {
            int idx = l * 256 + tid;
            int r = idx >> 2, kq = idx & 3;
            int row = row0 + r;
            float4 v = make_float4(0.f, 0.f, 0.f, 0.f);
            if (row < NN) v = *(const float4*)(X + (size_t)row * FIN + k0 + kq * 4);
            unsigned h, lo;
            split_tf32(v.x, h, lo); Ah[r][kq * 4 + 0] = h; Al[r][kq * 4 + 0] = lo;
            split_tf32(v.y, h, lo); Ah[r][kq * 4 + 1] = h; Al[r][kq * 4 + 1] = lo;
            split_tf32(v.z, h, lo); Ah[r][kq * 4 + 2] = h; Al[r][kq * 4 + 2] = lo;
            split_tf32(v.w, h, lo); Ah[r][kq * 4 + 3] = h; Al[r][kq * 4 + 3] = lo;
        }
        {
            int kr = tid >> 4, c4 = tid & 15;
            const float4 vh = *(const float4*)((const float*)WhG + (size_t)(k0 + kr) * 64 + c4 * 4);
            const float4 vl = *(const float4*)((const float*)WlG + (size_t)(k0 + kr) * 64 + c4 * 4);
            Bh[kr][c4 * 4 + 0] = __float_as_uint(vh.x);
            Bh[kr][c4 * 4 + 1] = __float_as_uint(vh.y);
            Bh[kr][c4 * 4 + 2] = __float_as_uint(vh.z);
            Bh[kr][c4 * 4 + 3] = __float_as_uint(vh.w);
            Bl[kr][c4 * 4 + 0] = __float_as_uint(vl.x);
            Bl[kr][c4 * 4 + 1] = __float_as_uint(vl.y);
            Bl[kr][c4 * 4 + 2] = __float_as_uint(vl.z);
            Bl[kr][c4 * 4 + 3] = __float_as_uint(vl.w);
        }
        __syncthreads();

        #pragma unroll
        for (int ks = 0; ks < 2; ++ks) {
            unsigned bh[4][2], bl[4][2];
            #pragma unroll
            for (int nt = 0; nt < 4; ++nt) {
                int c = wn * 32 + nt * 8 + g;
                bh[nt][0] = Bh[ks * 8 + tig][c];     bh[nt][1] = Bh[ks * 8 + tig + 4][c];
                bl[nt][0] = Bl[ks * 8 + tig][c];     bl[nt][1] = Bl[ks * 8 + tig + 4][c];
            }
            #pragma unroll
            for (int mt = 0; mt < 2; ++mt) {
                int rb = wm * 32 + mt * 16;
                unsigned ah[4], al[4];
                ah[0] = Ah[rb + g][ks * 8 + tig];       ah[1] = Ah[rb + g + 8][ks * 8 + tig];
                ah[2] = Ah[rb + g][ks * 8 + tig + 4];   ah[3] = Ah[rb + g + 8][ks * 8 + tig + 4];
                al[0] = Al[rb + g][ks * 8 + tig];       al[1] = Al[rb + g + 8][ks * 8 + tig];
                al[2] = Al[rb + g][ks * 8 + tig + 4];   al[3] = Al[rb + g + 8][ks * 8 + tig + 4];
                #pragma unroll
                for (int nt = 0; nt < 4; ++nt) {
                    mma_tf32(acc[mt][nt], ah, bh[nt]);
                    mma_tf32(acc[mt][nt], ah, bl[nt]);
                    mma_tf32(acc[mt][nt], al, bh[nt]);
                }
            }
        }
        __syncthreads();
    }

    // H store (fp16): one half2 per frag row (c even: c/2 = wn*16 + nt*4 + tig)
    #pragma unroll
    for (int mt = 0; mt < 2; ++mt)
        #pragma unroll
        for (int nt = 0; nt < 4; ++nt) {
            int r = row0 + wm * 32 + mt * 16 + g;
            int ch = wn * 16 + nt * 4 + tig;
            if (r < NN)
                g_h16[(size_t)r * 32 + ch] = __floats2half2_rn(acc[mt][nt][0], acc[mt][nt][1]);
            if (r + 8 < NN)
                g_h16[(size_t)(r + 8) * 32 + ch] = __floats2half2_rn(acc[mt][nt][2], acc[mt][nt][3]);
        }

    // attention projections from fp32 accumulators
    float asv[4][2], adv[4][2];
    #pragma unroll
    for (int nt = 0; nt < 4; ++nt) {
        int c = wn * 32 + nt * 8 + 2 * tig;
        asv[nt][0] = a_src[c]; asv[nt][1] = a_src[c + 1];
        adv[nt][0] = a_dst[c]; adv[nt][1] = a_dst[c + 1];
    }
    #pragma unroll
    for (int mt = 0; mt < 2; ++mt) {
        float s0 = 0.f, s1 = 0.f, d0 = 0.f, d1 = 0.f;
        #pragma unroll
        for (int nt = 0; nt < 4; ++nt) {
            s0 = fmaf(acc[mt][nt][0], asv[nt][0], fmaf(acc[mt][nt][1], asv[nt][1], s0));
            s1 = fmaf(acc[mt][nt][2], asv[nt][0], fmaf(acc[mt][nt][3], asv[nt][1], s1));
            d0 = fmaf(acc[mt][nt][0], adv[nt][0], fmaf(acc[mt][nt][1], adv[nt][1], d0));
            d1 = fmaf(acc[mt][nt][2], adv[nt][0], fmaf(acc[mt][nt][3], adv[nt][1], d1));
        }
        s0 += __shfl_xor_sync(0xffffffffu, s0, 1); s0 += __shfl_xor_sync(0xffffffffu, s0, 2);
        s1 += __shfl_xor_sync(0xffffffffu, s1, 1); s1 += __shfl_xor_sync(0xffffffffu, s1, 2);
        d0 += __shfl_xor_sync(0xffffffffu, d0, 1); d0 += __shfl_xor_sync(0xffffffffu, d0, 2);
        d1 += __shfl_xor_sync(0xffffffffu, d1, 1); d1 += __shfl_xor_sync(0xffffffffu, d1, 2);
        if (tig == 0) {
            int rl = wm * 32 + mt * 16 + g;
            sp_s[wn][rl] = s0; sp_s[wn][rl + 8] = s1;
            sp_d[wn][rl] = d0; sp_d[wn][rl + 8] = d1;
        }
    }
    __syncthreads();
    if (tid < 128) {
        int r = row0 + tid;
        if (r < NN) {
            g_as[r] = sp_s[0][tid] + sp_s[1][tid];
            g_ad[r] = sp_d[0][tid] + sp_d[1][tid];
        }
    }
}

// Fused layer-1: gemm blocks first, then scatter.
__global__ __launch_bounds__(256)
void k_fused1(const float* __restrict__ X,
              const float* __restrict__ a_src, const float* __restrict__ a_dst,
              const void* __restrict__ ei) {
    if ((int)blockIdx.x < GEMM_BLOCKS) {
        gemm_tc<128, false, true>(blockIdx.x, X, a_src, a_dst);
        return;
    }
    const int* e32 = (const int*)ei;
    bool is64 = detect_is64(e32);
    int i = ((int)blockIdx.x - GEMM_BLOCKS) * 256 + threadIdx.x;
    if (i >= TEg) return;
    int s, d;
    if (i < EE) {
        if (is64) {
            s = (int)((const long long*)ei)[i];
            d = (int)((const long long*)ei)[(long long)EE + i];
        } else {
            s = e32[i];
            d = e32[EE + i];
        }
    } else { s = i - EE; d = s; }
    if ((unsigned)d >= NN || (unsigned)s >= NN) return;
    int pos = atomicAdd(&g_cursor[d], 1);
    if ((unsigned)pos < TEg) g_srcidx[pos] = s;
}

__global__ __launch_bounds__(256)
void k_gemm2(const float* __restrict__ a_src, const float* __restrict__ a_dst) {
    gemm_tc<64, true, false>(blockIdx.x, nullptr, a_src, a_dst);
}

// ---------------- single-pass online-softmax aggregation ----------------
// One warp per destination node; lane owns features {2*lane, 2*lane+1}.
// Gather stream is fp16: one half2 (4B) per lane per edge.
template <bool WRITE_ACT>
__global__ __launch_bounds__(256)
void k_agg(const float* __restrict__ bias, float* __restrict__ OUText, int do_relu) {
    int w = (blockIdx.x * blockDim.x + threadIdx.x) >> 5;
    int lane = threadIdx.x & 31;
    if (w >= NN) return;

    float* OUT = WRITE_ACT ? (float*)g_act : OUText;

    int beg = g_rowptr[w], end = g_rowptr[w + 1];
    float adv = g_ad[w];

    float m = -1e30f;
    float acc0 = 0.f, acc1 = 0.f, denom = 0.f;

    for (int base = beg; base < end; base += 32) {
        int i = base + lane;
        float e = -1e30f;
        int s = 0;
        if (i < end) {
            s = g_srcidx[i];
            float t = g_as[s] + adv;
            e = (t > 0.f) ? t : NEG_SLOPE * t;
        }
        float bm = e;
        #pragma unroll
        for (int off = 16; off; off >>= 1)
            bm = fmaxf(bm, __shfl_xor_sync(0xffffffffu, bm, off));
        float mnew = fmaxf(m, bm);
        float scale = __expf(m - mnew);
        acc0 *= scale; acc1 *= scale; denom *= scale;
        m = mnew;

        float wgt = (i < end) ? __expf(e - mnew) : 0.f;
        denom += wgt;

        int cnt = end - base; if (cnt > 32) cnt = 32;
        int cnt4 = (cnt + 3) & ~3;
        for (int j = 0; j < cnt4; j += 4) {
            float wj0 = __shfl_sync(0xffffffffu, wgt, j);
            float wj1 = __shfl_sync(0xffffffffu, wgt, j + 1);
            float wj2 = __shfl_sync(0xffffffffu, wgt, j + 2);
            float wj3 = __shfl_sync(0xffffffffu, wgt, j + 3);
            int sj0 = __shfl_sync(0xffffffffu, s, j);
            int sj1 = __shfl_sync(0xffffffffu, s, j + 1);
            int sj2 = __shfl_sync(0xffffffffu, s, j + 2);
            int sj3 = __shfl_sync(0xffffffffu, s, j + 3);
            float2 f0 = __half22float2(g_h16[(size_t)sj0 * 32 + lane]);
            float2 f1 = __half22float2(g_h16[(size_t)sj1 * 32 + lane]);
            float2 f2 = __half22float2(g_h16[(size_t)sj2 * 32 + lane]);
            float2 f3 = __half22float2(g_h16[(size_t)sj3 * 32 + lane]);
            acc0 = fmaf(wj0, f0.x, acc0); acc1 = fmaf(wj0, f0.y, acc1);
            acc0 = fmaf(wj1, f1.x, acc0); acc1 = fmaf(wj1, f1.y, acc1);
            acc0 = fmaf(wj2, f2.x, acc0); acc1 = fmaf(wj2, f2.y, acc1);
            acc0 = fmaf(wj3, f3.x, acc0); acc1 = fmaf(wj3, f3.y, acc1);
        }
    }
    #pragma unroll
    for (int off = 16; off; off >>= 1)
        denom += __shfl_xor_sync(0xffffffffu, denom, off);

    float inv = 1.f / denom;
    float o0 = fmaf(acc0, inv, bias[2 * lane]);
    float o1 = fmaf(acc1, inv, bias[2 * lane + 1]);
    if (do_relu) { o0 = fmaxf(o0, 0.f); o1 = fmaxf(o1, 0.f); }
    *(float2*)(OUT + (size_t)w * 64 + 2 * lane) = make_float2(o0, o1);
}

// ---------------- launch ----------------
extern "C" void kernel_launch(void* const* d_in, const int* in_sizes, int n_in,
                              void* d_out, int out_size) {
    const float* x   = (const float*)d_in[0];
    const void*  ei  = d_in[1];                 // int32 or int64 — self-detected
    const float* W1  = (const float*)d_in[2];
    const float* a1s = (const float*)d_in[3];
    const float* a1d = (const float*)d_in[4];
    const float* b1  = (const float*)d_in[5];
    const float* W2  = (const float*)d_in[6];
    const float* a2s = (const float*)d_in[7];
    const float* a2d = (const float*)d_in[8];
    const float* b2  = (const float*)d_in[9];
    float* out = (float*)d_out;

    const int SCAN_BLOCKS = (NN + 511) / 512;   // 98
    const int WARP_GRID   = (NN * 32 + 255) / 256;

    // hist (+ fused W tf32-split) → scan → scan-combine
    k_hist  <<<SCAT_BLOCKS + WSPLIT_BLOCKS, 256>>>(ei, W1, W2);
    k_scan1 <<<SCAN_BLOCKS, 512>>>();
    k_scan3 <<<(NN + 255) / 256, 256>>>(SCAN_BLOCKS);

    // layer 1: tensor-core GEMM1 fused with CSR scatter
    k_fused1<<<GEMM_BLOCKS + SCAT_BLOCKS, 256>>>(x, a1s, a1d, ei);
    k_agg<true> <<<WARP_GRID, 256>>>(b1, out /*unused*/, 1);

    // layer 2
    k_gemm2 <<<GEMM_BLOCKS, 256>>>(a2s, a2d);
    k_agg<false><<<WARP_GRID, 256>>>(b2, out, 0);
}

// round 13
// speedup vs baseline: 1.2907x; 1.1048x over previous
#include <cuda_runtime.h>
#include <cuda_fp16.h>

#define NN 50000
#define EE 800000
#define TEg (EE + NN)          // edges + self loops
#define NEG_SLOPE 0.2f
#define SCAT_BLOCKS ((TEg + 255) / 256)   // 3321
#define GEMM_BLOCKS ((NN + 127) / 128)    // 391 (tensor-core tiles, 128 rows)
#define WSPLIT_BLOCKS 24                  // (64*64 + 32*64) k-pair entries / 256

// -------- static device scratch (no allocations allowed) --------
// g_cnt zero-at-start invariant: statically zeroed; k_scan1 re-zeroes after read.
__device__ __align__(16) __half2 g_h16[NN * 32];   // h in fp16 (gather stream)
__device__ __align__(16) float g_act[NN * 64];     // layer-1 activated output (fp32)
__device__ float g_as[NN];
__device__ float g_ad[NN];
__device__ int   g_cnt[NN];
__device__ int   g_rowptr[NN + 1];
__device__ int   g_cursor[NN];
__device__ int   g_srcidx[TEg];
__device__ int   g_bsums[128];
// W pre-split to fp16 hi/lo, packed as half2 over k-pairs: [k/2][64]
__device__ __align__(16) unsigned g_w1h[64 * 64];
__device__ __align__(16) unsigned g_w1l[64 * 64];
__device__ __align__(16) unsigned g_w2h[32 * 64];
__device__ __align__(16) unsigned g_w2l[32 * 64];

// fp16 split: x = hi + lo (11+11 mantissa bits ~ 22-bit effective)
__device__ __forceinline__ void split_f16(float x, __half& hi, __half& lo) {
    hi = __float2half_rn(x);
    lo = __float2half_rn(x - __half2float(hi));
}

__device__ __forceinline__ unsigned pack2(__half a, __half b) {
    __half2 t = __halves2half2(a, b);
    return *(unsigned*)&t;
}

__device__ __forceinline__ void mma_f16(float c[4], const unsigned a[4], const unsigned b[2]) {
    asm volatile(
        "mma.sync.aligned.m16n8k16.row.col.f32.f16.f16.f32 "
        "{%0,%1,%2,%3}, {%4,%5,%6,%7}, {%8,%9}, {%0,%1,%2,%3};"
        : "+f"(c[0]), "+f"(c[1]), "+f"(c[2]), "+f"(c[3])
        : "r"(a[0]), "r"(a[1]), "r"(a[2]), "r"(a[3]), "r"(b[0]), "r"(b[1]));
}

// Per-block dtype self-detection (int64 high halves of indices < 50000 are 0)
__device__ __forceinline__ bool detect_is64(const int* e32) {
    int any = __syncthreads_or(e32[2 * threadIdx.x + 1]);
    return any == 0;
}

// ---------------- CSR hist + (fused) weight split/pack ----------------
__global__ __launch_bounds__(256)
void k_hist(const void* __restrict__ ei, const float* __restrict__ W1,
            const float* __restrict__ W2) {
    if ((int)blockIdx.x >= SCAT_BLOCKS) {
        int idx = ((int)blockIdx.x - SCAT_BLOCKS) * 256 + threadIdx.x;
        const float* W; unsigned *Wh, *Wl; int j;
        if (idx < 64 * 64) { W = W1; Wh = g_w1h; Wl = g_w1l; j = idx; }
        else { W = W2; Wh = g_w2h; Wl = g_w2l; j = idx - 64 * 64; }   // j < 32*64
        int kp = j >> 6, n = j & 63;
        float x0 = W[(size_t)(2 * kp) * 64 + n];
        float x1 = W[(size_t)(2 * kp + 1) * 64 + n];
        __half h0, l0, h1, l1;
        split_f16(x0, h0, l0);
        split_f16(x1, h1, l1);
        Wh[j] = pack2(h0, h1);
        Wl[j] = pack2(l0, l1);
        return;
    }
    const int* e32 = (const int*)ei;
    bool is64 = detect_is64(e32);
    int i = blockIdx.x * 256 + threadIdx.x;
    if (i >= TEg) return;
    int d;
    if (i < EE)
        d = is64 ? (int)((const long long*)ei)[(long long)EE + i] : e32[EE + i];
    else
        d = i - EE;
    if ((unsigned)d < NN) atomicAdd(&g_cnt[d], 1);
}

// block-level inclusive scan (shfl-based); zeroes g_cnt after read
__global__ void k_scan1() {
    __shared__ int wsum[16];
    int t = threadIdx.x;
    int lane = t & 31, wid = t >> 5;
    int i = blockIdx.x * 512 + t;
    int v = 0;
    if (i < NN) { v = g_cnt[i]; g_cnt[i] = 0; }

    int s = v;
    #pragma unroll
    for (int off = 1; off < 32; off <<= 1) {
        int n = __shfl_up_sync(0xffffffffu, s, off);
        if (lane >= off) s += n;
    }
    if (lane == 31) wsum[wid] = s;
    __syncthreads();
    if (wid == 0) {
        int ws = (lane < 16) ? wsum[lane] : 0;
        #pragma unroll
        for (int off = 1; off < 16; off <<= 1) {
            int n = __shfl_up_sync(0xffffffffu, ws, off);
            if (lane >= off) ws += n;
        }
        if (lane < 16) wsum[lane] = ws;
    }
    __syncthreads();
    int base = (wid > 0) ? wsum[wid - 1] : 0;
    s += base;
    if (i < NN) g_rowptr[i + 1] = s;
    if (t == 511) g_bsums[blockIdx.x] = s;
}

__global__ __launch_bounds__(256) void k_scan3(int nblocks) {
    __shared__ int boff[128];
    __shared__ int wtot[4];
    int t = threadIdx.x;
    if (t < 128) {
        int lane = t & 31, wd = t >> 5;
        int v = (t < nblocks) ? g_bsums[t] : 0;
        int s = v;
        #pragma unroll
        for (int off = 1; off < 32; off <<= 1) {
            int n = __shfl_up_sync(0xffffffffu, s, off);
            if (lane >= off) s += n;
        }
        boff[t] = s;
        if (lane == 31) wtot[wd] = s;
    }
    __syncthreads();
    if (t < 128) {
        int wd = t >> 5;
        int add = 0;
        #pragma unroll
        for (int j = 0; j < 3; ++j)
            if (j < wd) add += wtot[j];
        boff[t] += add;
    }
    __syncthreads();
    int i = blockIdx.x * 256 + t;
    if (i == 0) { g_rowptr[0] = 0; g_cursor[0] = 0; }
    if (i < NN) {
        int blk = i >> 9;
        int off = (blk > 0) ? boff[blk - 1] : 0;
        int v = g_rowptr[i + 1] + off;
        g_rowptr[i + 1] = v;
        if (i + 1 < NN) g_cursor[i + 1] = v;
    }
}

// ---------------- tensor-core GEMM tile (fp16 2-way split, 3 products) ------
// H[N,64] = X[N,FIN] @ W[FIN,64]; H stored fp16; g_as/g_ad from fp32 accs.
// Block 256 thr = 8 warps (4 M x 2 N); block tile 128x64; warp tile 32x32.
// K-chunk 32 (2 x m16n8k16 steps per chunk).
template <int FIN, bool USE_ACT, bool LAYER1>
__device__ __forceinline__
void gemm_tc(int bid, const float* __restrict__ Xext,
             const float* __restrict__ a_src, const float* __restrict__ a_dst) {
    __shared__ unsigned A2h[128][18], A2l[128][18];   // 16 half2/row + pad
    __shared__ unsigned B2h[16][68],  B2l[16][68];    // 16 k-pairs x 64 n + pad
    __shared__ float sp_s[2][128], sp_d[2][128];

    const float* X = USE_ACT ? (const float*)g_act : Xext;
    const unsigned* WhG = LAYER1 ? g_w1h : g_w2h;
    const unsigned* WlG = LAYER1 ? g_w1l : g_w2l;

    int tid = threadIdx.x;
    int lane = tid & 31, wid = tid >> 5;
    int wm = wid >> 1, wn = wid & 1;
    int g = lane >> 2, tig = lane & 3;
    int row0 = bid * 128;

    float acc[2][4][4] = {};

    for (int k0 = 0; k0 < FIN; k0 += 32) {
        // A chunk 128x32: 1024 float4, 4/thread; split+pack to half2 hi/lo
        #pragma unroll
        for (int l = 0; l < 4; ++l) {
            int idx = l * 256 + tid;
            int r = idx >> 3, q = idx & 7;
            int row = row0 + r;
            float4 v = make_float4(0.f, 0.f, 0.f, 0.f);
            if (row < NN) v = *(const float4*)(X + (size_t)row * FIN + k0 + q * 4);
            __half hx, lx, hy, ly;
            split_f16(v.x, hx, lx); split_f16(v.y, hy, ly);
            A2h[r][q * 2] = pack2(hx, hy);
            A2l[r][q * 2] = pack2(lx, ly);
            split_f16(v.z, hx, lx); split_f16(v.w, hy, ly);
            A2h[r][q * 2 + 1] = pack2(hx, hy);
            A2l[r][q * 2 + 1] = pack2(lx, ly);
        }
        // B chunk: 16 k-pairs x 64 n, pre-packed in gmem
        {
            int kp0 = k0 >> 1;   // first k-pair of chunk
            #pragma unroll
            for (int l = 0; l < 4; ++l) {
                int idx = l * 256 + tid;
                int kr = idx >> 6, n = idx & 63;
                B2h[kr][n] = WhG[(size_t)(kp0 + kr) * 64 + n];
                B2l[kr][n] = WlG[(size_t)(kp0 + kr) * 64 + n];
            }
        }
        __syncthreads();

        #pragma unroll
        for (int ks = 0; ks < 2; ++ks) {
            unsigned bh[4][2], bl[4][2];
            #pragma unroll
            for (int nt = 0; nt < 4; ++nt) {
                int c = wn * 32 + nt * 8 + g;
                bh[nt][0] = B2h[ks * 8 + tig][c];     bh[nt][1] = B2h[ks * 8 + tig + 4][c];
                bl[nt][0] = B2l[ks * 8 + tig][c];     bl[nt][1] = B2l[ks * 8 + tig + 4][c];
            }
            #pragma unroll
            for (int mt = 0; mt < 2; ++mt) {
                int rb = wm * 32 + mt * 16;
                unsigned ah[4], al[4];
                ah[0] = A2h[rb + g][ks * 8 + tig];       ah[1] = A2h[rb + g + 8][ks * 8 + tig];
                ah[2] = A2h[rb + g][ks * 8 + tig + 4];   ah[3] = A2h[rb + g + 8][ks * 8 + tig + 4];
                al[0] = A2l[rb + g][ks * 8 + tig];       al[1] = A2l[rb + g + 8][ks * 8 + tig];
                al[2] = A2l[rb + g][ks * 8 + tig + 4];   al[3] = A2l[rb + g + 8][ks * 8 + tig + 4];
                #pragma unroll
                for (int nt = 0; nt < 4; ++nt) {
                    mma_f16(acc[mt][nt], ah, bh[nt]);
                    mma_f16(acc[mt][nt], ah, bl[nt]);
                    mma_f16(acc[mt][nt], al, bh[nt]);
                }
            }
        }
        __syncthreads();
    }

    // H store (fp16): one half2 per frag row (c even: c/2 = wn*16 + nt*4 + tig)
    #pragma unroll
    for (int mt = 0; mt < 2; ++mt)
        #pragma unroll
        for (int nt = 0; nt < 4; ++nt) {
            int r = row0 + wm * 32 + mt * 16 + g;
            int ch = wn * 16 + nt * 4 + tig;
            if (r < NN)
                g_h16[(size_t)r * 32 + ch] = __floats2half2_rn(acc[mt][nt][0], acc[mt][nt][1]);
            if (r + 8 < NN)
                g_h16[(size_t)(r + 8) * 32 + ch] = __floats2half2_rn(acc[mt][nt][2], acc[mt][nt][3]);
        }

    // attention projections from fp32 accumulators
    float asv[4][2], adv[4][2];
    #pragma unroll
    for (int nt = 0; nt < 4; ++nt) {
        int c = wn * 32 + nt * 8 + 2 * tig;
        asv[nt][0] = a_src[c]; asv[nt][1] = a_src[c + 1];
        adv[nt][0] = a_dst[c]; adv[nt][1] = a_dst[c + 1];
    }
    #pragma unroll
    for (int mt = 0; mt < 2; ++mt) {
        float s0 = 0.f, s1 = 0.f, d0 = 0.f, d1 = 0.f;
        #pragma unroll
        for (int nt = 0; nt < 4; ++nt) {
            s0 = fmaf(acc[mt][nt][0], asv[nt][0], fmaf(acc[mt][nt][1], asv[nt][1], s0));
            s1 = fmaf(acc[mt][nt][2], asv[nt][0], fmaf(acc[mt][nt][3], asv[nt][1], s1));
            d0 = fmaf(acc[mt][nt][0], adv[nt][0], fmaf(acc[mt][nt][1], adv[nt][1], d0));
            d1 = fmaf(acc[mt][nt][2], adv[nt][0], fmaf(acc[mt][nt][3], adv[nt][1], d1));
        }
        s0 += __shfl_xor_sync(0xffffffffu, s0, 1); s0 += __shfl_xor_sync(0xffffffffu, s0, 2);
        s1 += __shfl_xor_sync(0xffffffffu, s1, 1); s1 += __shfl_xor_sync(0xffffffffu, s1, 2);
        d0 += __shfl_xor_sync(0xffffffffu, d0, 1); d0 += __shfl_xor_sync(0xffffffffu, d0, 2);
        d1 += __shfl_xor_sync(0xffffffffu, d1, 1); d1 += __shfl_xor_sync(0xffffffffu, d1, 2);
        if (tig == 0) {
            int rl = wm * 32 + mt * 16 + g;
            sp_s[wn][rl] = s0; sp_s[wn][rl + 8] = s1;
            sp_d[wn][rl] = d0; sp_d[wn][rl + 8] = d1;
        }
    }
    __syncthreads();
    if (tid < 128) {
        int r = row0 + tid;
        if (r < NN) {
            g_as[r] = sp_s[0][tid] + sp_s[1][tid];
            g_ad[r] = sp_d[0][tid] + sp_d[1][tid];
        }
    }
}

// Fused layer-1: gemm blocks first, then scatter.
__global__ __launch_bounds__(256)
void k_fused1(const float* __restrict__ X,
              const float* __restrict__ a_src, const float* __restrict__ a_dst,
              const void* __restrict__ ei) {
    if ((int)blockIdx.x < GEMM_BLOCKS) {
        gemm_tc<128, false, true>(blockIdx.x, X, a_src, a_dst);
        return;
    }
    const int* e32 = (const int*)ei;
    bool is64 = detect_is64(e32);
    int i = ((int)blockIdx.x - GEMM_BLOCKS) * 256 + threadIdx.x;
    if (i >= TEg) return;
    int s, d;
    if (i < EE) {
        if (is64) {
            s = (int)((const long long*)ei)[i];
            d = (int)((const long long*)ei)[(long long)EE + i];
        } else {
            s = e32[i];
            d = e32[EE + i];
        }
    } else { s = i - EE; d = s; }
    if ((unsigned)d >= NN || (unsigned)s >= NN) return;
    int pos = atomicAdd(&g_cursor[d], 1);
    if ((unsigned)pos < TEg) g_srcidx[pos] = s;
}

__global__ __launch_bounds__(256)
void k_gemm2(const float* __restrict__ a_src, const float* __restrict__ a_dst) {
    gemm_tc<64, true, false>(blockIdx.x, nullptr, a_src, a_dst);
}

// ---------------- single-pass online-softmax aggregation ----------------
// One warp per destination node; lane owns features {2*lane, 2*lane+1}.
template <bool WRITE_ACT>
__global__ __launch_bounds__(256)
void k_agg(const float* __restrict__ bias, float* __restrict__ OUText, int do_relu) {
    int w = (blockIdx.x * blockDim.x + threadIdx.x) >> 5;
    int lane = threadIdx.x & 31;
    if (w >= NN) return;

    float* OUT = WRITE_ACT ? (float*)g_act : OUText;

    int beg = g_rowptr[w], end = g_rowptr[w + 1];
    float adv = g_ad[w];

    float m = -1e30f;
    float acc0 = 0.f, acc1 = 0.f, denom = 0.f;

    for (int base = beg; base < end; base += 32) {
        int i = base + lane;
        float e = -1e30f;
        int s = 0;
        if (i < end) {
            s = g_srcidx[i];
            float t = g_as[s] + adv;
            e = (t > 0.f) ? t : NEG_SLOPE * t;
        }
        float bm = e;
        #pragma unroll
        for (int off = 16; off; off >>= 1)
            bm = fmaxf(bm, __shfl_xor_sync(0xffffffffu, bm, off));
        float mnew = fmaxf(m, bm);
        float scale = __expf(m - mnew);
        acc0 *= scale; acc1 *= scale; denom *= scale;
        m = mnew;

        float wgt = (i < end) ? __expf(e - mnew) : 0.f;
        denom += wgt;

        int cnt = end - base; if (cnt > 32) cnt = 32;
        int cnt4 = (cnt + 3) & ~3;
        for (int j = 0; j < cnt4; j += 4) {
            float wj0 = __shfl_sync(0xffffffffu, wgt, j);
            float wj1 = __shfl_sync(0xffffffffu, wgt, j + 1);
            float wj2 = __shfl_sync(0xffffffffu, wgt, j + 2);
            float wj3 = __shfl_sync(0xffffffffu, wgt, j + 3);
            int sj0 = __shfl_sync(0xffffffffu, s, j);
            int sj1 = __shfl_sync(0xffffffffu, s, j + 1);
            int sj2 = __shfl_sync(0xffffffffu, s, j + 2);
            int sj3 = __shfl_sync(0xffffffffu, s, j + 3);
            float2 f0 = __half22float2(g_h16[(size_t)sj0 * 32 + lane]);
            float2 f1 = __half22float2(g_h16[(size_t)sj1 * 32 + lane]);
            float2 f2 = __half22float2(g_h16[(size_t)sj2 * 32 + lane]);
            float2 f3 = __half22float2(g_h16[(size_t)sj3 * 32 + lane]);
            acc0 = fmaf(wj0, f0.x, acc0); acc1 = fmaf(wj0, f0.y, acc1);
            acc0 = fmaf(wj1, f1.x, acc0); acc1 = fmaf(wj1, f1.y, acc1);
            acc0 = fmaf(wj2, f2.x, acc0); acc1 = fmaf(wj2, f2.y, acc1);
            acc0 = fmaf(wj3, f3.x, acc0); acc1 = fmaf(wj3, f3.y, acc1);
        }
    }
    #pragma unroll
    for (int off = 16; off; off >>= 1)
        denom += __shfl_xor_sync(0xffffffffu, denom, off);

    float inv = 1.f / denom;
    float o0 = fmaf(acc0, inv, bias[2 * lane]);
    float o1 = fmaf(acc1, inv, bias[2 * lane + 1]);
    if (do_relu) { o0 = fmaxf(o0, 0.f); o1 = fmaxf(o1, 0.f); }
    *(float2*)(OUT + (size_t)w * 64 + 2 * lane) = make_float2(o0, o1);
}

// ---------------- launch ----------------
extern "C" void kernel_launch(void* const* d_in, const int* in_sizes, int n_in,
                              void* d_out, int out_size) {
    const float* x   = (const float*)d_in[0];
    const void*  ei  = d_in[1];                 // int32 or int64 — self-detected
    const float* W1  = (const float*)d_in[2];
    const float* a1s = (const float*)d_in[3];
    const float* a1d = (const float*)d_in[4];
    const float* b1  = (const float*)d_in[5];
    const float* W2  = (const float*)d_in[6];
    const float* a2s = (const float*)d_in[7];
    const float* a2d = (const float*)d_in[8];
    const float* b2  = (const float*)d_in[9];
    float* out = (float*)d_out;

    const int SCAN_BLOCKS = (NN + 511) / 512;   // 98
    const int WARP_GRID   = (NN * 32 + 255) / 256;

    // hist (+ fused W fp16 split/pack) → scan → scan-combine
    k_hist  <<<SCAT_BLOCKS + WSPLIT_BLOCKS, 256>>>(ei, W1, W2);
    k_scan1 <<<SCAN_BLOCKS, 512>>>();
    k_scan3 <<<(NN + 255) / 256, 256>>>(SCAN_BLOCKS);

    // layer 1: tensor-core GEMM1 fused with CSR scatter
    k_fused1<<<GEMM_BLOCKS + SCAT_BLOCKS, 256>>>(x, a1s, a1d, ei);
    k_agg<true> <<<WARP_GRID, 256>>>(b1, out /*unused*/, 1);

    // layer 2
    k_gemm2 <<<GEMM_BLOCKS, 256>>>(a2s, a2d);
    k_agg<false><<<WARP_GRID, 256>>>(b2, out, 0);
}

// round 14
// speedup vs baseline: 1.3201x; 1.0228x over previous
#include <cuda_runtime.h>
#include <cuda_fp16.h>

#define NN 50000
#define EE 800000
#define TEg (EE + NN)          // edges + self loops
#define NEG_SLOPE 0.2f
#define SCAT_BLOCKS ((TEg + 255) / 256)   // 3321
#define GEMM_BLOCKS ((NN + 127) / 128)    // 391 (tensor-core tiles, 128 rows)
#define WSPLIT_BLOCKS 24                  // (64*64 + 32*64) k-pair entries / 256

// -------- static device scratch (no allocations allowed) --------
// g_cnt zero-at-start invariant: statically zeroed; k_scan1 re-zeroes after read.
__device__ __align__(16) __half2 g_h16[NN * 32];   // h in fp16 (gather stream)
__device__ __align__(16) __half2 g_act16[NN * 32]; // layer-1 activated output (fp16)
__device__ float g_as[NN];
__device__ float g_ad[NN];
__device__ int   g_cnt[NN];
__device__ int   g_rowptr[NN + 1];
__device__ int   g_cursor[NN];
__device__ int   g_srcidx[TEg];
__device__ int   g_bsums[128];
// W pre-split to fp16 hi/lo, packed as half2 over k-pairs: [k/2][64]
__device__ __align__(16) unsigned g_w1h[64 * 64];
__device__ __align__(16) unsigned g_w1l[64 * 64];
__device__ __align__(16) unsigned g_w2h[32 * 64];
__device__ __align__(16) unsigned g_w2l[32 * 64];

// fp16 split: x = hi + lo (11+11 mantissa bits ~ 22-bit effective)
__device__ __forceinline__ void split_f16(float x, __half& hi, __half& lo) {
    hi = __float2half_rn(x);
    lo = __float2half_rn(x - __half2float(hi));
}

__device__ __forceinline__ unsigned pack2(__half a, __half b) {
    __half2 t = __halves2half2(a, b);
    return *(unsigned*)&t;
}

__device__ __forceinline__ void mma_f16(float c[4], const unsigned a[4], const unsigned b[2]) {
    asm volatile(
        "mma.sync.aligned.m16n8k16.row.col.f32.f16.f16.f32 "
        "{%0,%1,%2,%3}, {%4,%5,%6,%7}, {%8,%9}, {%0,%1,%2,%3};"
        : "+f"(c[0]), "+f"(c[1]), "+f"(c[2]), "+f"(c[3])
        : "r"(a[0]), "r"(a[1]), "r"(a[2]), "r"(a[3]), "r"(b[0]), "r"(b[1]));
}

// Per-block dtype self-detection (int64 high halves of indices < 50000 are 0)
__device__ __forceinline__ bool detect_is64(const int* e32) {
    int any = __syncthreads_or(e32[2 * threadIdx.x + 1]);
    return any == 0;
}

// ---------------- CSR hist + (fused) weight split/pack ----------------
__global__ __launch_bounds__(256)
void k_hist(const void* __restrict__ ei, const float* __restrict__ W1,
            const float* __restrict__ W2) {
    if ((int)blockIdx.x >= SCAT_BLOCKS) {
        int idx = ((int)blockIdx.x - SCAT_BLOCKS) * 256 + threadIdx.x;
        const float* W; unsigned *Wh, *Wl; int j;
        if (idx < 64 * 64) { W = W1; Wh = g_w1h; Wl = g_w1l; j = idx; }
        else { W = W2; Wh = g_w2h; Wl = g_w2l; j = idx - 64 * 64; }   // j < 32*64
        int kp = j >> 6, n = j & 63;
        float x0 = W[(size_t)(2 * kp) * 64 + n];
        float x1 = W[(size_t)(2 * kp + 1) * 64 + n];
        __half h0, l0, h1, l1;
        split_f16(x0, h0, l0);
        split_f16(x1, h1, l1);
        Wh[j] = pack2(h0, h1);
        Wl[j] = pack2(l0, l1);
        return;
    }
    const int* e32 = (const int*)ei;
    bool is64 = detect_is64(e32);
    int i = blockIdx.x * 256 + threadIdx.x;
    if (i >= TEg) return;
    int d;
    if (i < EE)
        d = is64 ? (int)((const long long*)ei)[(long long)EE + i] : e32[EE + i];
    else
        d = i - EE;
    if ((unsigned)d < NN) atomicAdd(&g_cnt[d], 1);
}

// block-level inclusive scan (shfl-based); zeroes g_cnt after read
__global__ void k_scan1() {
    __shared__ int wsum[16];
    int t = threadIdx.x;
    int lane = t & 31, wid = t >> 5;
    int i = blockIdx.x * 512 + t;
    int v = 0;
    if (i < NN) { v = g_cnt[i]; g_cnt[i] = 0; }

    int s = v;
    #pragma unroll
    for (int off = 1; off < 32; off <<= 1) {
        int n = __shfl_up_sync(0xffffffffu, s, off);
        if (lane >= off) s += n;
    }
    if (lane == 31) wsum[wid] = s;
    __syncthreads();
    if (wid == 0) {
        int ws = (lane < 16) ? wsum[lane] : 0;
        #pragma unroll
        for (int off = 1; off < 16; off <<= 1) {
            int n = __shfl_up_sync(0xffffffffu, ws, off);
            if (lane >= off) ws += n;
        }
        if (lane < 16) wsum[lane] = ws;
    }
    __syncthreads();
    int base = (wid > 0) ? wsum[wid - 1] : 0;
    s += base;
    if (i < NN) g_rowptr[i + 1] = s;
    if (t == 511) g_bsums[blockIdx.x] = s;
}

__global__ __launch_bounds__(256) void k_scan3(int nblocks) {
    __shared__ int boff[128];
    __shared__ int wtot[4];
    int t = threadIdx.x;
    if (t < 128) {
        int lane = t & 31, wd = t >> 5;
        int v = (t < nblocks) ? g_bsums[t] : 0;
        int s = v;
        #pragma unroll
        for (int off = 1; off < 32; off <<= 1) {
            int n = __shfl_up_sync(0xffffffffu, s, off);
            if (lane >= off) s += n;
        }
        boff[t] = s;
        if (lane == 31) wtot[wd] = s;
    }
    __syncthreads();
    if (t < 128) {
        int wd = t >> 5;
        int add = 0;
        #pragma unroll
        for (int j = 0; j < 3; ++j)
            if (j < wd) add += wtot[j];
        boff[t] += add;
    }
    __syncthreads();
    int i = blockIdx.x * 256 + t;
    if (i == 0) { g_rowptr[0] = 0; g_cursor[0] = 0; }
    if (i < NN) {
        int blk = i >> 9;
        int off = (blk > 0) ? boff[blk - 1] : 0;
        int v = g_rowptr[i + 1] + off;
        g_rowptr[i + 1] = v;
        if (i + 1 < NN) g_cursor[i + 1] = v;
    }
}

// ---------------- tensor-core GEMM tile (A fp16, B 2-way split) ------------
// H[N,64] = X[N,FIN] @ W[FIN,64]; H stored fp16; g_as/g_ad from fp32 accs.
// Block 256 thr = 8 warps (4 M x 2 N); block tile 128x64; warp tile 32x32.
// K-chunk 32 (2 x m16n8k16 steps); products: Ah*Bh + Ah*Bl.
template <int FIN, bool USE_ACT, bool LAYER1>
__device__ __forceinline__
void gemm_tc(int bid, const float* __restrict__ Xext,
             const float* __restrict__ a_src, const float* __restrict__ a_dst) {
    __shared__ unsigned A2[128][20];                 // 16 half2/row + pad (16B-aligned rows)
    __shared__ unsigned B2h[16][68], B2l[16][68];    // 16 k-pairs x 64 n + pad
    __shared__ float sp_s[2][128], sp_d[2][128];

    const unsigned* WhG = LAYER1 ? g_w1h : g_w2h;
    const unsigned* WlG = LAYER1 ? g_w1l : g_w2l;

    int tid = threadIdx.x;
    int lane = tid & 31, wid = tid >> 5;
    int wm = wid >> 1, wn = wid & 1;
    int g = lane >> 2, tig = lane & 3;
    int row0 = bid * 128;

    float acc[2][4][4] = {};

    for (int k0 = 0; k0 < FIN; k0 += 32) {
        // ---- A chunk 128x32 into smem (fp16 half2 over k-pairs) ----
        if (USE_ACT) {
            // act is already fp16: 128 rows x 16 half2 = 512 uint4, 2/thread
            #pragma unroll
            for (int l = 0; l < 2; ++l) {
                int idx = l * 256 + tid;
                int r = idx >> 2, q4 = idx & 3;
                int row = row0 + r;
                uint4 v = make_uint4(0u, 0u, 0u, 0u);
                if (row < NN)
                    v = *(const uint4*)((const unsigned*)g_act16 + (size_t)row * 32 + (k0 >> 1) + q4 * 4);
                *(uint4*)(&A2[r][q4 * 4]) = v;
            }
        } else {
            // X fp32: 1024 float4, 4/thread; convert to half2, store uint2
            #pragma unroll
            for (int l = 0; l < 4; ++l) {
                int idx = l * 256 + tid;
                int r = idx >> 3, q = idx & 7;
                int row = row0 + r;
                float4 v = make_float4(0.f, 0.f, 0.f, 0.f);
                if (row < NN) v = *(const float4*)(Xext + (size_t)row * FIN + k0 + q * 4);
                __half2 p0 = __floats2half2_rn(v.x, v.y);
                __half2 p1 = __floats2half2_rn(v.z, v.w);
                uint2 st = make_uint2(*(unsigned*)&p0, *(unsigned*)&p1);
                *(uint2*)(&A2[r][q * 2]) = st;
            }
        }
        // ---- B chunk: 16 k-pairs x 64 n (pre-split hi/lo in gmem) ----
        {
            int kp0 = k0 >> 1;
            #pragma unroll
            for (int l = 0; l < 4; ++l) {
                int idx = l * 256 + tid;
                int kr = idx >> 6, n = idx & 63;
                B2h[kr][n] = WhG[(size_t)(kp0 + kr) * 64 + n];
                B2l[kr][n] = WlG[(size_t)(kp0 + kr) * 64 + n];
            }
        }
        __syncthreads();

        #pragma unroll
        for (int ks = 0; ks < 2; ++ks) {
            unsigned bh[4][2], bl[4][2];
            #pragma unroll
            for (int nt = 0; nt < 4; ++nt) {
                int c = wn * 32 + nt * 8 + g;
                bh[nt][0] = B2h[ks * 8 + tig][c];     bh[nt][1] = B2h[ks * 8 + tig + 4][c];
                bl[nt][0] = B2l[ks * 8 + tig][c];     bl[nt][1] = B2l[ks * 8 + tig + 4][c];
            }
            #pragma unroll
            for (int mt = 0; mt < 2; ++mt) {
                int rb = wm * 32 + mt * 16;
                unsigned ah[4];
                ah[0] = A2[rb + g][ks * 8 + tig];
                ah[1] = A2[rb + g + 8][ks * 8 + tig];
                ah[2] = A2[rb + g][ks * 8 + tig + 4];
                ah[3] = A2[rb + g + 8][ks * 8 + tig + 4];
                #pragma unroll
                for (int nt = 0; nt < 4; ++nt) {
                    mma_f16(acc[mt][nt], ah, bh[nt]);
                    mma_f16(acc[mt][nt], ah, bl[nt]);
                }
            }
        }
        __syncthreads();
    }

    // H store (fp16): one half2 per frag row (c even: c/2 = wn*16 + nt*4 + tig)
    #pragma unroll
    for (int mt = 0; mt < 2; ++mt)
        #pragma unroll
        for (int nt = 0; nt < 4; ++nt) {
            int r = row0 + wm * 32 + mt * 16 + g;
            int ch = wn * 16 + nt * 4 + tig;
            if (r < NN)
                g_h16[(size_t)r * 32 + ch] = __floats2half2_rn(acc[mt][nt][0], acc[mt][nt][1]);
            if (r + 8 < NN)
                g_h16[(size_t)(r + 8) * 32 + ch] = __floats2half2_rn(acc[mt][nt][2], acc[mt][nt][3]);
        }

    // attention projections from fp32 accumulators
    float asv[4][2], adv[4][2];
    #pragma unroll
    for (int nt = 0; nt < 4; ++nt) {
        int c = wn * 32 + nt * 8 + 2 * tig;
        asv[nt][0] = a_src[c]; asv[nt][1] = a_src[c + 1];
        adv[nt][0] = a_dst[c]; adv[nt][1] = a_dst[c + 1];
    }
    #pragma unroll
    for (int mt = 0; mt < 2; ++mt) {
        float s0 = 0.f, s1 = 0.f, d0 = 0.f, d1 = 0.f;
        #pragma unroll
        for (int nt = 0; nt < 4; ++nt) {
            s0 = fmaf(acc[mt][nt][0], asv[nt][0], fmaf(acc[mt][nt][1], asv[nt][1], s0));
            s1 = fmaf(acc[mt][nt][2], asv[nt][0], fmaf(acc[mt][nt][3], asv[nt][1], s1));
            d0 = fmaf(acc[mt][nt][0], adv[nt][0], fmaf(acc[mt][nt][1], adv[nt][1], d0));
            d1 = fmaf(acc[mt][nt][2], adv[nt][0], fmaf(acc[mt][nt][3], adv[nt][1], d1));
        }
        s0 += __shfl_xor_sync(0xffffffffu, s0, 1); s0 += __shfl_xor_sync(0xffffffffu, s0, 2);
        s1 += __shfl_xor_sync(0xffffffffu, s1, 1); s1 += __shfl_xor_sync(0xffffffffu, s1, 2);
        d0 += __shfl_xor_sync(0xffffffffu, d0, 1); d0 += __shfl_xor_sync(0xffffffffu, d0, 2);
        d1 += __shfl_xor_sync(0xffffffffu, d1, 1); d1 += __shfl_xor_sync(0xffffffffu, d1, 2);
        if (tig == 0) {
            int rl = wm * 32 + mt * 16 + g;
            sp_s[wn][rl] = s0; sp_s[wn][rl + 8] = s1;
            sp_d[wn][rl] = d0; sp_d[wn][rl + 8] = d1;
        }
    }
    __syncthreads();
    if (tid < 128) {
        int r = row0 + tid;
        if (r < NN) {
            g_as[r] = sp_s[0][tid] + sp_s[1][tid];
            g_ad[r] = sp_d[0][tid] + sp_d[1][tid];
        }
    }
}

// Fused layer-1: gemm blocks first, then scatter.
__global__ __launch_bounds__(256)
void k_fused1(const float* __restrict__ X,
              const float* __restrict__ a_src, const float* __restrict__ a_dst,
              const void* __restrict__ ei) {
    if ((int)blockIdx.x < GEMM_BLOCKS) {
        gemm_tc<128, false, true>(blockIdx.x, X, a_src, a_dst);
        return;
    }
    const int* e32 = (const int*)ei;
    bool is64 = detect_is64(e32);
    int i = ((int)blockIdx.x - GEMM_BLOCKS) * 256 + threadIdx.x;
    if (i >= TEg) return;
    int s, d;
    if (i < EE) {
        if (is64) {
            s = (int)((const long long*)ei)[i];
            d = (int)((const long long*)ei)[(long long)EE + i];
        } else {
            s = e32[i];
            d = e32[EE + i];
        }
    } else { s = i - EE; d = s; }
    if ((unsigned)d >= NN || (unsigned)s >= NN) return;
    int pos = atomicAdd(&g_cursor[d], 1);
    if ((unsigned)pos < TEg) g_srcidx[pos] = s;
}

__global__ __launch_bounds__(256)
void k_gemm2(const float* __restrict__ a_src, const float* __restrict__ a_dst) {
    gemm_tc<64, true, false>(blockIdx.x, nullptr, a_src, a_dst);
}

// ---------------- single-pass online-softmax aggregation ----------------
// One warp per destination node; lane owns features {2*lane, 2*lane+1}.
template <bool WRITE_ACT>
__global__ __launch_bounds__(256)
void k_agg(const float* __restrict__ bias, float* __restrict__ OUText, int do_relu) {
    int w = (blockIdx.x * blockDim.x + threadIdx.x) >> 5;
    int lane = threadIdx.x & 31;
    if (w >= NN) return;

    int beg = g_rowptr[w], end = g_rowptr[w + 1];
    float adv = g_ad[w];

    float m = -1e30f;
    float acc0 = 0.f, acc1 = 0.f, denom = 0.f;

    for (int base = beg; base < end; base += 32) {
        int i = base + lane;
        float e = -1e30f;
        int s = 0;
        if (i < end) {
            s = g_srcidx[i];
            float t = g_as[s] + adv;
            e = (t > 0.f) ? t : NEG_SLOPE * t;
        }
        float bm = e;
        #pragma unroll
        for (int off = 16; off; off >>= 1)
            bm = fmaxf(bm, __shfl_xor_sync(0xffffffffu, bm, off));
        float mnew = fmaxf(m, bm);
        float scale = __expf(m - mnew);
        acc0 *= scale; acc1 *= scale; denom *= scale;
        m = mnew;

        float wgt = (i < end) ? __expf(e - mnew) : 0.f;
        denom += wgt;

        int cnt = end - base; if (cnt > 32) cnt = 32;
        int cnt4 = (cnt + 3) & ~3;
        for (int j = 0; j < cnt4; j += 4) {
            float wj0 = __shfl_sync(0xffffffffu, wgt, j);
            float wj1 = __shfl_sync(0xffffffffu, wgt, j + 1);
            float wj2 = __shfl_sync(0xffffffffu, wgt, j + 2);
            float wj3 = __shfl_sync(0xffffffffu, wgt, j + 3);
            int sj0 = __shfl_sync(0xffffffffu, s, j);
            int sj1 = __shfl_sync(0xffffffffu, s, j + 1);
            int sj2 = __shfl_sync(0xffffffffu, s, j + 2);
            int sj3 = __shfl_sync(0xffffffffu, s, j + 3);
            float2 f0 = __half22float2(g_h16[(size_t)sj0 * 32 + lane]);
            float2 f1 = __half22float2(g_h16[(size_t)sj1 * 32 + lane]);
            float2 f2 = __half22float2(g_h16[(size_t)sj2 * 32 + lane]);
            float2 f3 = __half22float2(g_h16[(size_t)sj3 * 32 + lane]);
            acc0 = fmaf(wj0, f0.x, acc0); acc1 = fmaf(wj0, f0.y, acc1);
            acc0 = fmaf(wj1, f1.x, acc0); acc1 = fmaf(wj1, f1.y, acc1);
            acc0 = fmaf(wj2, f2.x, acc0); acc1 = fmaf(wj2, f2.y, acc1);
            acc0 = fmaf(wj3, f3.x, acc0); acc1 = fmaf(wj3, f3.y, acc1);
        }
    }
    #pragma unroll
    for (int off = 16; off; off >>= 1)
        denom += __shfl_xor_sync(0xffffffffu, denom, off);

    float inv = 1.f / denom;
    float o0 = fmaf(acc0, inv, bias[2 * lane]);
    float o1 = fmaf(acc1, inv, bias[2 * lane + 1]);
    if (do_relu) { o0 = fmaxf(o0, 0.f); o1 = fmaxf(o1, 0.f); }
    if (WRITE_ACT) {
        g_act16[(size_t)w * 32 + lane] = __floats2half2_rn(o0, o1);
    } else {
        *(float2*)(OUText + (size_t)w * 64 + 2 * lane) = make_float2(o0, o1);
    }
}

// ---------------- launch ----------------
extern "C" void kernel_launch(void* const* d_in, const int* in_sizes, int n_in,
                              void* d_out, int out_size) {
    const float* x   = (const float*)d_in[0];
    const void*  ei  = d_in[1];                 // int32 or int64 — self-detected
    const float* W1  = (const float*)d_in[2];
    const float* a1s = (const float*)d_in[3];
    const float* a1d = (const float*)d_in[4];
    const float* b1  = (const float*)d_in[5];
    const float* W2  = (const float*)d_in[6];
    const float* a2s = (const float*)d_in[7];
    const float* a2d = (const float*)d_in[8];
    const float* b2  = (const float*)d_in[9];
    float* out = (float*)d_out;

    const int SCAN_BLOCKS = (NN + 511) / 512;   // 98
    const int WARP_GRID   = (NN * 32 + 255) / 256;

    // hist (+ fused W fp16 split/pack) → scan → scan-combine
    k_hist  <<<SCAT_BLOCKS + WSPLIT_BLOCKS, 256>>>(ei, W1, W2);
    k_scan1 <<<SCAN_BLOCKS, 512>>>();
    k_scan3 <<<(NN + 255) / 256, 256>>>(SCAN_BLOCKS);

    // layer 1: tensor-core GEMM1 fused with CSR scatter
    k_fused1<<<GEMM_BLOCKS + SCAT_BLOCKS, 256>>>(x, a1s, a1d, ei);
    k_agg<true> <<<WARP_GRID, 256>>>(b1, out /*unused*/, 1);

    // layer 2
    k_gemm2 <<<GEMM_BLOCKS, 256>>>(a2s, a2d);
    k_agg<false><<<WARP_GRID, 256>>>(b2, out, 0);
}